// round 2
// baseline (speedup 1.0000x reference)
#include <cuda_runtime.h>
#include <math.h>

// Problem constants (B=1)
#define LL   2048
#define DD   512
#define KK   64
#define TWOK 128
#define CH   128   // chunk length
#define NCH  16    // number of chunks
#define PI_F 3.14159265358979323846f

static __device__ float g_Hke[LL*DD];
static __device__ float g_Hqe[LL*DD];
static __device__ float g_pk [LL*KK];
static __device__ float g_pq [LL*KK];
static __device__ float g_amp[LL*KK];
static __device__ float g_V  [LL*DD];
static __device__ float g_Qc [LL*TWOK];
static __device__ float g_Kc [LL*TWOK];
static __device__ float g_G  [NCH*TWOK*DD];
static __device__ float g_Sx [NCH*TWOK*DD];
static __device__ float g_P  [NCH*CH*CH];
static __device__ float g_ret[LL*DD];
static __device__ float g_rn [LL*DD];

// ---------------------------------------------------------------------------
// f32x2 helpers (Blackwell packed fp32 — exact IEEE fp32 per lane)
// ---------------------------------------------------------------------------
__device__ __forceinline__ void ffma2(unsigned long long& d,
                                      unsigned long long a,
                                      unsigned long long b)
{
    asm("fma.rn.f32x2 %0, %1, %2, %0;" : "+l"(d) : "l"(a), "l"(b));
}
__device__ __forceinline__ unsigned long long dup2(float a)
{
    unsigned long long r; unsigned int u = __float_as_uint(a);
    asm("mov.b64 %0, {%1, %1};" : "=l"(r) : "r"(u));
    return r;
}
__device__ __forceinline__ void unpack2(unsigned long long v, float& lo, float& hi)
{
    unsigned int a, b;
    asm("mov.b64 {%0, %1}, %2;" : "=r"(a), "=r"(b) : "l"(v));
    lo = __uint_as_float(a); hi = __uint_as_float(b);
}

// ---------------------------------------------------------------------------
// Shared GEMM body: C = epi( [C +] opA(A) @ opB(B) + bias )
// Double-buffered smem, float4 global loads, f32x2 FMA inner loop.
// epi (runtime): 0 none, 1 exact GELU, 2 tanh*pi, 3 softplus+0.1,
//                4 +X residual, 5 causal mask, 6 rsqrt((l+1)K) scale
// ---------------------------------------------------------------------------
template<int BM,int BN,int BK,int TM,int TN,bool TRA,bool TRB,bool ACC>
__device__ __forceinline__ void gemm_body(
    const float* __restrict__ A, const float* __restrict__ B,
    const float* __restrict__ bias, const float* __restrict__ X,
    float* __restrict__ C, int epi, int zscale,
    int M, int N, int Kd, int lda, int ldb, int ldc)
{
    constexpr int PAD = 4;
    constexpr int NT  = (BM/TM)*(BN/TN);     // must equal 256
    __shared__ __align__(16) float As[2][BK][BM+PAD];
    __shared__ __align__(16) float Bs[2][BK][BN];

    const int tid = threadIdx.x;
    const int tx  = tid % (BN/TN);
    const int ty  = tid / (BN/TN);
    const int m0  = blockIdx.y * BM;
    const int n0  = blockIdx.x * BN;

    constexpr int A4 = BM*BK/4;
    constexpr int B4 = BN*BK/4;
    constexpr int AV = (A4 + NT - 1)/NT;
    constexpr int BV = (B4 + NT - 1)/NT;
    constexpr bool AFULL = (A4 % NT) == 0;
    constexpr bool BFULL = (B4 % NT) == 0;

    float4 pa[AV], pb[BV];

    auto loadA = [&](int k0){
#pragma unroll
        for (int r = 0; r < AV; r++){
            int v = tid + r*NT;
            if (AFULL || v < A4){
                if (TRA){ int k = v/(BM/4), m4 = v%(BM/4);
                    pa[r] = *(const float4*)&A[(long)(k0+k)*lda + m0 + 4*m4];
                } else { int m = v/(BK/4), k4 = v%(BK/4);
                    pa[r] = *(const float4*)&A[(long)(m0+m)*lda + k0 + 4*k4];
                }
            }
        }
    };
    auto storeA = [&](int buf){
#pragma unroll
        for (int r = 0; r < AV; r++){
            int v = tid + r*NT;
            if (AFULL || v < A4){
                if (TRA){ int k = v/(BM/4), m4 = v%(BM/4);
                    *(float4*)&As[buf][k][4*m4] = pa[r];
                } else { int m = v/(BK/4), k4 = v%(BK/4);
                    As[buf][4*k4+0][m] = pa[r].x;
                    As[buf][4*k4+1][m] = pa[r].y;
                    As[buf][4*k4+2][m] = pa[r].z;
                    As[buf][4*k4+3][m] = pa[r].w;
                }
            }
        }
    };
    auto loadB = [&](int k0){
#pragma unroll
        for (int r = 0; r < BV; r++){
            int v = tid + r*NT;
            if (BFULL || v < B4){
                if (TRB){ int n = v/(BK/4), k4 = v%(BK/4);
                    pb[r] = *(const float4*)&B[(long)(n0+n)*ldb + k0 + 4*k4];
                } else { int k = v/(BN/4), n4 = v%(BN/4);
                    pb[r] = *(const float4*)&B[(long)(k0+k)*ldb + n0 + 4*n4];
                }
            }
        }
    };
    auto storeB = [&](int buf){
#pragma unroll
        for (int r = 0; r < BV; r++){
            int v = tid + r*NT;
            if (BFULL || v < B4){
                if (TRB){ int n = v/(BK/4), k4 = v%(BK/4);
                    Bs[buf][4*k4+0][n] = pb[r].x;
                    Bs[buf][4*k4+1][n] = pb[r].y;
                    Bs[buf][4*k4+2][n] = pb[r].z;
                    Bs[buf][4*k4+3][n] = pb[r].w;
                } else { int k = v/(BN/4), n4 = v%(BN/4);
                    *(float4*)&Bs[buf][k][4*n4] = pb[r];
                }
            }
        }
    };

    unsigned long long acc[TM][TN/2];
#pragma unroll
    for (int i = 0; i < TM; i++)
#pragma unroll
        for (int j = 0; j < TN/2; j++) acc[i][j] = 0ull;

    loadA(0); loadB(0);
    storeA(0); storeB(0);
    __syncthreads();

    const int nk = Kd / BK;
    for (int it = 0; it < nk; ++it){
        const int cur = it & 1;
        if (it + 1 < nk){ loadA((it+1)*BK); loadB((it+1)*BK); }

#pragma unroll
        for (int k = 0; k < BK; k++){
            unsigned long long a2[TM], b2[TN/2];
#pragma unroll
            for (int i = 0; i < TM; i++)
                a2[i] = dup2(As[cur][k][ty*TM + i]);
#pragma unroll
            for (int j = 0; j < TN/2; j++)
                b2[j] = *(const unsigned long long*)&Bs[cur][k][tx*TN + 2*j];
#pragma unroll
            for (int i = 0; i < TM; i++)
#pragma unroll
                for (int j = 0; j < TN/2; j++)
                    ffma2(acc[i][j], a2[i], b2[j]);
        }

        if (it + 1 < nk){ storeA(cur ^ 1); storeB(cur ^ 1); }
        __syncthreads();
    }

    // Epilogue
#pragma unroll
    for (int i = 0; i < TM; i++){
        const int m = m0 + ty*TM + i;
#pragma unroll
        for (int j = 0; j < TN/2; j++){
            float vlo, vhi; unpack2(acc[i][j], vlo, vhi);
            float vv[2] = {vlo, vhi};
#pragma unroll
            for (int t = 0; t < 2; t++){
                const int n = n0 + tx*TN + 2*j + t;
                const long idx = (long)m*ldc + n;
                float v = vv[t];
                if (ACC) v += C[idx];
                if (bias) v += bias[n];
                if      (epi == 1) v = 0.5f*v*(1.f + erff(v*0.70710678118654752f));
                else if (epi == 2) v = tanhf(v)*PI_F;
                else if (epi == 3) v = (v > 20.f ? v : log1pf(expf(v))) + 0.1f;
                else if (epi == 4) v += X[idx];
                else if (epi == 5) v = (n <= m) ? v : 0.f;
                else if (epi == 6) v *= rsqrtf((float)(zscale*M + m + 1)*(float)KK);
                C[idx] = v;
            }
        }
    }
}

// ---------------------------------------------------------------------------
// Wrappers
// ---------------------------------------------------------------------------
struct MultiArgs {
    const float* A[3]; const float* B[3]; const float* bias[3];
    float* C[3]; int epi[3];
};

template<int BM,int BN,int BK,int TM,int TN>
__launch_bounds__(256)
__global__ void gemm_multi(MultiArgs ma, int M,int N,int Kd,int lda,int ldb,int ldc)
{
    const int z = blockIdx.z;
    gemm_body<BM,BN,BK,TM,TN,false,false,false>(
        ma.A[z], ma.B[z], ma.bias[z], nullptr, ma.C[z], ma.epi[z], 0,
        M, N, Kd, lda, ldb, ldc);
}

template<int BM,int BN,int BK,int TM,int TN,bool TRA,bool TRB,bool ACC>
__launch_bounds__(256)
__global__ void gemm_str(const float* A, const float* B, const float* bias,
                         const float* X, float* C, int epi,
                         int M,int N,int Kd,int lda,int ldb,int ldc,
                         long sA, long sB, long sC)
{
    const int z = blockIdx.z;
    gemm_body<BM,BN,BK,TM,TN,TRA,TRB,ACC>(
        A + (long)z*sA, B + (long)z*sB, bias, X, C + (long)z*sC, epi, z,
        M, N, Kd, lda, ldb, ldc);
}

// ---------------------------------------------------------------------------
// phasors: Qc = [amp*cos(pq) | amp*sin(pq)], Kc = [amp*cos(pk) | amp*sin(pk)]
// ---------------------------------------------------------------------------
__global__ void phasor_k()
{
    int idx = blockIdx.x * blockDim.x + threadIdx.x;
    if (idx >= LL * KK) return;
    int l = idx / KK, k = idx % KK;
    float a = g_amp[idx];
    float s, c;
    sincosf(g_pk[idx], &s, &c);
    g_Kc[l * TWOK + k]      = a * c;
    g_Kc[l * TWOK + KK + k] = a * s;
    sincosf(g_pq[idx], &s, &c);
    g_Qc[l * TWOK + k]      = a * c;
    g_Qc[l * TWOK + KK + k] = a * s;
}

// exclusive prefix over chunks of G -> Sx
__global__ void scan_k()
{
    int idx = blockIdx.x * blockDim.x + threadIdx.x;
    if (idx >= TWOK * DD) return;
    float run = 0.f;
#pragma unroll
    for (int c = 0; c < NCH; c++) {
        g_Sx[c * (TWOK * DD) + idx] = run;
        run += g_G[c * (TWOK * DD) + idx];
    }
}

// LayerNorm over D=512, eps 1e-5. One block (256 thr) per row.
__global__ void ln_k(const float* __restrict__ in, const float* __restrict__ g,
                     const float* __restrict__ b, float* __restrict__ out)
{
    const int row = blockIdx.x;
    const int tid = threadIdx.x;
    const float* r = in + (long)row * DD;

    float v0 = r[tid], v1 = r[tid + 256];

    __shared__ float sh[256];
    sh[tid] = v0 + v1;
    __syncthreads();
#pragma unroll
    for (int o = 128; o > 0; o >>= 1) {
        if (tid < o) sh[tid] += sh[tid + o];
        __syncthreads();
    }
    float mu = sh[0] * (1.f / DD);
    __syncthreads();

    float d0 = v0 - mu, d1 = v1 - mu;
    sh[tid] = d0 * d0 + d1 * d1;
    __syncthreads();
#pragma unroll
    for (int o = 128; o > 0; o >>= 1) {
        if (tid < o) sh[tid] += sh[tid + o];
        __syncthreads();
    }
    float inv = rsqrtf(sh[0] * (1.f / DD) + 1e-5f);

    out[(long)row * DD + tid]       = d0 * inv * g[tid]       + b[tid];
    out[(long)row * DD + tid + 256] = d1 * inv * g[tid + 256] + b[tid + 256];
}

// ---------------------------------------------------------------------------
extern "C" void kernel_launch(void* const* d_in, const int* in_sizes, int n_in,
                              void* d_out, int out_size)
{
    const float* x     = (const float*)d_in[0];
    const float* ke_w1 = (const float*)d_in[1];
    const float* ke_b1 = (const float*)d_in[2];
    const float* ke_w2 = (const float*)d_in[3];
    const float* ke_b2 = (const float*)d_in[4];
    const float* qe_w1 = (const float*)d_in[5];
    const float* qe_b1 = (const float*)d_in[6];
    const float* qe_w2 = (const float*)d_in[7];
    const float* qe_b2 = (const float*)d_in[8];
    const float* amp_w = (const float*)d_in[9];
    const float* amp_b = (const float*)d_in[10];
    const float* v_w   = (const float*)d_in[11];
    const float* v_b   = (const float*)d_in[12];
    const float* ln_g  = (const float*)d_in[13];
    const float* ln_b  = (const float*)d_in[14];
    const float* out_w = (const float*)d_in[15];
    const float* out_b = (const float*)d_in[16];
    float* out = (float*)d_out;

    float *Hke,*Hqe,*pk,*pq,*amp,*V,*Qc,*Kc,*G,*Sx,*P,*ret,*rn;
    cudaGetSymbolAddress((void**)&Hke, g_Hke);
    cudaGetSymbolAddress((void**)&Hqe, g_Hqe);
    cudaGetSymbolAddress((void**)&pk,  g_pk);
    cudaGetSymbolAddress((void**)&pq,  g_pq);
    cudaGetSymbolAddress((void**)&amp, g_amp);
    cudaGetSymbolAddress((void**)&V,   g_V);
    cudaGetSymbolAddress((void**)&Qc,  g_Qc);
    cudaGetSymbolAddress((void**)&Kc,  g_Kc);
    cudaGetSymbolAddress((void**)&G,   g_G);
    cudaGetSymbolAddress((void**)&Sx,  g_Sx);
    cudaGetSymbolAddress((void**)&P,   g_P);
    cudaGetSymbolAddress((void**)&ret, g_ret);
    cudaGetSymbolAddress((void**)&rn,  g_rn);

    const dim3 T(256);

    // 1) Fused big encoder+V GEMMs: {Hke, Hqe, V} = {gelu,gelu,id}(x @ W + b)
    {
        MultiArgs a;
        a.A[0]=x;     a.A[1]=x;     a.A[2]=x;
        a.B[0]=ke_w1; a.B[1]=qe_w1; a.B[2]=v_w;
        a.bias[0]=ke_b1; a.bias[1]=qe_b1; a.bias[2]=v_b;
        a.C[0]=Hke;   a.C[1]=Hqe;   a.C[2]=V;
        a.epi[0]=1;   a.epi[1]=1;   a.epi[2]=0;
        gemm_multi<64,128,16,4,8><<<dim3(DD/128, LL/64, 3), T>>>(
            a, LL, DD, DD, DD, DD, DD);
    }

    // 2) Fused narrow projections: pk, pq, amp
    {
        MultiArgs a;
        a.A[0]=Hke;   a.A[1]=Hqe;   a.A[2]=x;
        a.B[0]=ke_w2; a.B[1]=qe_w2; a.B[2]=amp_w;
        a.bias[0]=ke_b2; a.bias[1]=qe_b2; a.bias[2]=amp_b;
        a.C[0]=pk;    a.C[1]=pq;    a.C[2]=amp;
        a.epi[0]=2;   a.epi[1]=2;   a.epi[2]=3;
        gemm_multi<32,64,16,2,4><<<dim3(1, LL/32, 3), T>>>(
            a, LL, KK, DD, DD, KK, KK);
    }

    // 3) phasors
    phasor_k<<<(LL*KK + 255)/256, 256>>>();

    // 4) G_c = Kc_c^T @ V_c  (batched over 16 chunks)
    gemm_str<64,128,16,4,8,true,false,false>
        <<<dim3(DD/128, TWOK/64, NCH), T>>>(Kc, V, nullptr, nullptr, G, 0,
            TWOK, DD, CH, TWOK, DD, DD,
            (long)CH*TWOK, (long)CH*DD, (long)TWOK*DD);

    // 5) exclusive chunk scan -> Sx
    scan_k<<<(TWOK*DD + 255)/256, 256>>>();

    // 6) P_c = tril(Qc_c @ Kc_c^T)
    gemm_str<32,64,16,2,4,false,true,false>
        <<<dim3(CH/64, CH/32, NCH), T>>>(Qc, Kc, nullptr, nullptr, P, 5,
            CH, CH, TWOK, TWOK, TWOK, CH,
            (long)CH*TWOK, (long)CH*TWOK, (long)CH*CH);

    // 7) ret_c = Qc_c @ Sx_c
    gemm_str<64,128,16,4,8,false,false,false>
        <<<dim3(DD/128, CH/64, NCH), T>>>(Qc, Sx, nullptr, nullptr, ret, 0,
            CH, DD, TWOK, TWOK, DD, DD,
            (long)CH*TWOK, (long)TWOK*DD, (long)CH*DD);

    // 8) ret_c = (ret_c + P_c @ V_c) * rsqrt((l+1)*K)
    gemm_str<64,128,16,4,8,false,false,true>
        <<<dim3(DD/128, CH/64, NCH), T>>>(P, V, nullptr, nullptr, ret, 6,
            CH, DD, CH, CH, DD, DD,
            (long)CH*CH, (long)CH*DD, (long)CH*DD);

    // 9) LayerNorm
    ln_k<<<LL, 256>>>(ret, ln_g, ln_b, rn);

    // 10) out = x + rn @ out_w + out_b
    gemm_str<64,128,16,4,8,false,false,false>
        <<<dim3(DD/128, LL/64, 1), T>>>(rn, out_w, out_b, x, out, 4,
            LL, DD, DD, DD, DD, DD, 0, 0, 0);

    (void)in_sizes; (void)n_in; (void)out_size;
}

// round 3
// speedup vs baseline: 1.0335x; 1.0335x over previous
#include <cuda_runtime.h>
#include <cuda_bf16.h>
#include <math.h>

#define LL   2048
#define DD   512
#define KK   64
#define TWOK 128
#define CH   128
#define NCH  16
#define PI_F 3.14159265358979323846f

typedef __nv_bfloat16 bf16;

// ------------------------------ buffers -----------------------------------
static __device__ bf16  g_xhi [LL*DD],      g_xlo [LL*DD];
static __device__ bf16  g_w1th[3*DD*DD],    g_w1tl[3*DD*DD];   // ke1,qe1,v (transposed)
static __device__ bf16  g_owth[DD*DD],      g_owtl[DD*DD];
static __device__ bf16  g_w2th[3*KK*DD],    g_w2tl[3*KK*DD];   // ke2,qe2,amp (transposed)
static __device__ bf16  g_Hkeh[LL*DD],      g_Hkel[LL*DD];
static __device__ bf16  g_Hqeh[LL*DD],      g_Hqel[LL*DD];
static __device__ bf16  g_VTh [DD*LL],      g_VTl [DD*LL];
static __device__ float g_pk  [LL*KK], g_pq[LL*KK], g_amp[LL*KK];
static __device__ bf16  g_Qch [LL*TWOK],    g_Qcl [LL*TWOK];
static __device__ bf16  g_Kch [LL*TWOK],    g_Kcl [LL*TWOK];
static __device__ bf16  g_KcTh[TWOK*LL],    g_KcTl[TWOK*LL];
static __device__ float g_G   [NCH*TWOK*DD];
static __device__ bf16  g_SxTh[NCH*DD*TWOK],g_SxTl[NCH*DD*TWOK];
static __device__ bf16  g_Ph  [NCH*CH*CH],  g_Pl  [NCH*CH*CH];
static __device__ float g_ret [LL*DD];
static __device__ bf16  g_rnh [LL*DD],      g_rnl [LL*DD];

// ------------------------------ PTX helpers --------------------------------
__device__ __forceinline__ void ldmat4(unsigned& r0, unsigned& r1,
                                       unsigned& r2, unsigned& r3, unsigned addr)
{
    asm volatile("ldmatrix.sync.aligned.m8n8.x4.shared.b16 {%0,%1,%2,%3}, [%4];\n"
                 : "=r"(r0), "=r"(r1), "=r"(r2), "=r"(r3) : "r"(addr));
}
__device__ __forceinline__ void mma16816(float* c, const unsigned* a, const unsigned* b)
{
    asm volatile("mma.sync.aligned.m16n8k16.row.col.f32.bf16.bf16.f32 "
                 "{%0,%1,%2,%3}, {%4,%5,%6,%7}, {%8,%9}, {%0,%1,%2,%3};\n"
                 : "+f"(c[0]), "+f"(c[1]), "+f"(c[2]), "+f"(c[3])
                 : "r"(a[0]), "r"(a[1]), "r"(a[2]), "r"(a[3]), "r"(b[0]), "r"(b[1]));
}
__device__ __forceinline__ void cpasync16(unsigned dst, const void* src)
{
    asm volatile("cp.async.ca.shared.global [%0], [%1], 16;\n" :: "r"(dst), "l"(src));
}
__device__ __forceinline__ void split_store(bf16* hi, bf16* lo, size_t i, float v)
{
    bf16 h = __float2bfloat16_rn(v);
    hi[i] = h;
    lo[i] = __float2bfloat16_rn(v - __bfloat162float(h));
}

// ------------------------------ GEMM arg -----------------------------------
struct GArg {
    const bf16 *Ahi, *Alo, *Bhi, *Blo;
    const float *bias, *X, *Cin;
    float *Cf;
    bf16 *Chi, *Clo;
    int epi;        // 0 none,1 gelu,2 tanh*pi,3 softplus+0.1,4 +X,5 causal,6 norm-scale
    int transOut;   // hilo stored transposed
    int ldh;        // leading dim of hilo store
    int mglob0;     // global m offset (epi 6)
};

// ------------------------------ GEMM body ----------------------------------
// C(M,N) = epi( [Cin +] A(M,K) @ Bt(N,K)^T + bias ), 3-way bf16 split.
template<int BM, int BN>
__device__ __forceinline__ void mma_gemm_body(
    GArg g, int M, int N, int Kd, int lda, int ldb, int ldc)
{
    constexpr int BK = 32, PK = 40;
    constexpr int ASZ = 2 * BM * PK;     // elems per buffer (both splits)
    constexpr int BSZ = 2 * BN * PK;
    extern __shared__ bf16 dyn[];
    bf16* Abuf = dyn;                    // [2][ASZ]
    bf16* Bbuf = dyn + 2 * ASZ;          // [2][BSZ]
    const unsigned sA0 = (unsigned)__cvta_generic_to_shared(Abuf);
    const unsigned sB0 = (unsigned)__cvta_generic_to_shared(Bbuf);

    const int tid = threadIdx.x, lane = tid & 31, warp = tid >> 5;
    const int m0 = blockIdx.y * BM, n0 = blockIdx.x * BN;
    const int wm = (warp & 3) * (BM / 4), wn = (warp >> 2) * (BN / 2);
    constexpr int MT  = (BM / 4) / 16;    // 2
    constexpr int NT8 = (BN / 2) / 8;     // 8 (BN=128) or 4 (BN=64)

    float c[MT][NT8][4];
#pragma unroll
    for (int i = 0; i < MT; i++)
#pragma unroll
        for (int j = 0; j < NT8; j++)
#pragma unroll
            for (int e = 0; e < 4; e++) c[i][j][e] = 0.f;

    auto load_tile = [&](int buf, int k0) {
        constexpr int ACH = BM * 8;       // 16B chunks: rows * 2 splits * 4
#pragma unroll
        for (int q = 0; q < ACH / 256; q++) {
            int idx = q * 256 + tid, row = idx >> 3, sub = idx & 7;
            int s = sub >> 2, kc = sub & 3;
            const bf16* src = (s ? g.Alo : g.Ahi)
                              + (size_t)(m0 + row) * lda + k0 + kc * 8;
            unsigned dst = sA0 + (unsigned)((buf * ASZ + (s * BM + row) * PK + kc * 8) * 2);
            cpasync16(dst, src);
        }
        constexpr int BCH = BN * 8;
#pragma unroll
        for (int q = 0; q < BCH / 256; q++) {
            int idx = q * 256 + tid, row = idx >> 3, sub = idx & 7;
            int s = sub >> 2, kc = sub & 3;
            const bf16* src = (s ? g.Blo : g.Bhi)
                              + (size_t)(n0 + row) * ldb + k0 + kc * 8;
            unsigned dst = sB0 + (unsigned)((buf * BSZ + (s * BN + row) * PK + kc * 8) * 2);
            cpasync16(dst, src);
        }
        asm volatile("cp.async.commit_group;\n");
    };

    const int a_row = lane & 15, a_col = (lane >> 4) * 8;
    const int gq = lane >> 3, rr = lane & 7;
    const int b_row = ((gq >> 1) << 3) + rr, b_col = (gq & 1) * 8;

    load_tile(0, 0);
    const int nk = Kd / BK;
    for (int it = 0; it < nk; ++it) {
        if (it + 1 < nk) {
            load_tile((it + 1) & 1, (it + 1) * BK);
            asm volatile("cp.async.wait_group 1;\n");
        } else {
            asm volatile("cp.async.wait_group 0;\n");
        }
        __syncthreads();
        const int buf = it & 1;
        const unsigned aBase = sA0 + (unsigned)(buf * ASZ * 2);
        const unsigned bBase = sB0 + (unsigned)(buf * BSZ * 2);
#pragma unroll
        for (int kk = 0; kk < 2; ++kk) {
            const int ks = kk * 16;
            unsigned af[2][MT][4];
#pragma unroll
            for (int s = 0; s < 2; s++)
#pragma unroll
                for (int mt = 0; mt < MT; mt++) {
                    unsigned addr = aBase + (unsigned)(((s * BM + wm + mt * 16 + a_row) * PK
                                                       + ks + a_col) * 2);
                    ldmat4(af[s][mt][0], af[s][mt][1], af[s][mt][2], af[s][mt][3], addr);
                }
            unsigned bfr[2][NT8][2];
#pragma unroll
            for (int s = 0; s < 2; s++)
#pragma unroll
                for (int p = 0; p < NT8 / 2; p++) {
                    unsigned r0, r1, r2, r3;
                    unsigned addr = bBase + (unsigned)(((s * BN + wn + p * 16 + b_row) * PK
                                                       + ks + b_col) * 2);
                    ldmat4(r0, r1, r2, r3, addr);
                    bfr[s][2 * p][0] = r0;  bfr[s][2 * p][1] = r1;
                    bfr[s][2 * p + 1][0] = r2;  bfr[s][2 * p + 1][1] = r3;
                }
#pragma unroll
            for (int mt = 0; mt < MT; mt++)
#pragma unroll
                for (int nt = 0; nt < NT8; nt++) {
                    mma16816(c[mt][nt], af[0][mt], bfr[0][nt]);   // hi@hi
                    mma16816(c[mt][nt], af[0][mt], bfr[1][nt]);   // hi@lo
                    mma16816(c[mt][nt], af[1][mt], bfr[0][nt]);   // lo@hi
                }
        }
        __syncthreads();
    }

    // ---------------- epilogue ----------------
#pragma unroll
    for (int mt = 0; mt < MT; mt++)
#pragma unroll
        for (int nt = 0; nt < NT8; nt++)
#pragma unroll
            for (int e = 0; e < 4; e++) {
                int m = m0 + wm + mt * 16 + (lane >> 2) + ((e >> 1) << 3);
                int n = n0 + wn + nt * 8 + ((lane & 3) << 1) + (e & 1);
                float v = c[mt][nt][e];
                if (g.Cin)  v += g.Cin[(size_t)m * ldc + n];
                if (g.bias) v += g.bias[n];
                switch (g.epi) {
                    case 1: v = 0.5f * v * (1.f + erff(v * 0.70710678118654752f)); break;
                    case 2: v = tanhf(v) * PI_F; break;
                    case 3: v = (v > 20.f ? v : log1pf(expf(v))) + 0.1f; break;
                    case 4: v += g.X[(size_t)m * ldc + n]; break;
                    case 5: if (n > m) v = 0.f; break;
                    case 6: v *= rsqrtf((float)(g.mglob0 + m + 1) * (float)KK); break;
                }
                if (g.Cf) g.Cf[(size_t)m * ldc + n] = v;
                if (g.Chi) {
                    size_t oi = g.transOut ? ((size_t)n * g.ldh + m)
                                           : ((size_t)m * g.ldh + n);
                    split_store(g.Chi, g.Clo, oi, v);
                }
            }
}

template<int BM, int BN>
__launch_bounds__(256)
__global__ void gemm_multi3(GArg a0, GArg a1, GArg a2,
                            int M, int N, int Kd, int lda, int ldb, int ldc)
{
    GArg g = (blockIdx.z == 0) ? a0 : (blockIdx.z == 1) ? a1 : a2;
    mma_gemm_body<BM, BN>(g, M, N, Kd, lda, ldb, ldc);
}

template<int BM, int BN>
__launch_bounds__(256)
__global__ void gemm_chunk(GArg g, long sA, long sB, long sCf, long sCh,
                           int M, int N, int Kd, int lda, int ldb, int ldc)
{
    const int z = blockIdx.z;
    g.Ahi += (size_t)z * sA;  g.Alo += (size_t)z * sA;
    g.Bhi += (size_t)z * sB;  g.Blo += (size_t)z * sB;
    if (g.Cf)  g.Cf  += (size_t)z * sCf;
    if (g.Cin) g.Cin += (size_t)z * sCf;
    if (g.Chi) { g.Chi += (size_t)z * sCh; g.Clo += (size_t)z * sCh; }
    g.mglob0 = z * M;
    mma_gemm_body<BM, BN>(g, M, N, Kd, lda, ldb, ldc);
}

// ------------------------------ prep kernels -------------------------------
__global__ void convx_k(const float* __restrict__ x)
{
    int i = blockIdx.x * 256 + threadIdx.x;
    if (i < LL * DD) split_store(g_xhi, g_xlo, i, x[i]);
}

struct WTJob { const float* src; bf16 *dhi, *dlo; int K, N; };
struct WTJobs { WTJob j[7]; };
__global__ void wtrans_k(WTJobs jobs)
{
    WTJob w = jobs.j[blockIdx.z];
    int total = w.K * w.N;
    for (int i = blockIdx.x * 256 + threadIdx.x; i < total; i += gridDim.x * 256) {
        int k = i / w.N, n = i % w.N;
        split_store(w.dhi, w.dlo, (size_t)n * w.K + k, w.src[i]);
    }
}

__global__ void phasor_k()
{
    int idx = blockIdx.x * 256 + threadIdx.x;
    if (idx >= LL * KK) return;
    int l = idx / KK, k = idx % KK;
    float a = g_amp[idx];
    float s, cc;
    sincosf(g_pk[idx], &s, &cc);
    float kr = a * cc, ki = a * s;
    split_store(g_Kch,  g_Kcl,  (size_t)l * TWOK + k,        kr);
    split_store(g_Kch,  g_Kcl,  (size_t)l * TWOK + KK + k,   ki);
    split_store(g_KcTh, g_KcTl, (size_t)k * LL + l,          kr);
    split_store(g_KcTh, g_KcTl, (size_t)(k + KK) * LL + l,   ki);
    sincosf(g_pq[idx], &s, &cc);
    split_store(g_Qch, g_Qcl, (size_t)l * TWOK + k,      a * cc);
    split_store(g_Qch, g_Qcl, (size_t)l * TWOK + KK + k, a * s);
}

__global__ void scan_k()
{
    int idx = blockIdx.x * 256 + threadIdx.x;
    if (idx >= TWOK * DD) return;
    int kk = idx / DD, d = idx % DD;
    float run = 0.f;
#pragma unroll
    for (int cchunk = 0; cchunk < NCH; cchunk++) {
        split_store(g_SxTh, g_SxTl,
                    (size_t)cchunk * DD * TWOK + (size_t)d * TWOK + kk, run);
        run += g_G[(size_t)cchunk * TWOK * DD + (size_t)kk * DD + d];
    }
}

__global__ void ln_k(const float* __restrict__ in, const float* __restrict__ gam,
                     const float* __restrict__ bet)
{
    const int row = blockIdx.x, tid = threadIdx.x;
    const float* r = in + (size_t)row * DD;
    float v0 = r[tid], v1 = r[tid + 256];

    __shared__ float sh[256];
    sh[tid] = v0 + v1;
    __syncthreads();
#pragma unroll
    for (int o = 128; o > 0; o >>= 1) { if (tid < o) sh[tid] += sh[tid + o]; __syncthreads(); }
    float mu = sh[0] * (1.f / DD);
    __syncthreads();
    float d0 = v0 - mu, d1 = v1 - mu;
    sh[tid] = d0 * d0 + d1 * d1;
    __syncthreads();
#pragma unroll
    for (int o = 128; o > 0; o >>= 1) { if (tid < o) sh[tid] += sh[tid + o]; __syncthreads(); }
    float inv = rsqrtf(sh[0] * (1.f / DD) + 1e-5f);

    split_store(g_rnh, g_rnl, (size_t)row * DD + tid,       d0 * inv * gam[tid] + bet[tid]);
    split_store(g_rnh, g_rnl, (size_t)row * DD + tid + 256, d1 * inv * gam[tid + 256] + bet[tid + 256]);
}

// ------------------------------ host ---------------------------------------
extern "C" void kernel_launch(void* const* d_in, const int* in_sizes, int n_in,
                              void* d_out, int out_size)
{
    const float* x     = (const float*)d_in[0];
    const float* ke_w1 = (const float*)d_in[1];
    const float* ke_b1 = (const float*)d_in[2];
    const float* ke_w2 = (const float*)d_in[3];
    const float* ke_b2 = (const float*)d_in[4];
    const float* qe_w1 = (const float*)d_in[5];
    const float* qe_b1 = (const float*)d_in[6];
    const float* qe_w2 = (const float*)d_in[7];
    const float* qe_b2 = (const float*)d_in[8];
    const float* amp_w = (const float*)d_in[9];
    const float* amp_b = (const float*)d_in[10];
    const float* v_w   = (const float*)d_in[11];
    const float* v_b   = (const float*)d_in[12];
    const float* ln_g  = (const float*)d_in[13];
    const float* ln_b  = (const float*)d_in[14];
    const float* out_w = (const float*)d_in[15];
    const float* out_b = (const float*)d_in[16];
    float* out = (float*)d_out;

    // resolve device symbols
    bf16 *xhi, *xlo, *w1th, *w1tl, *owth, *owtl, *w2th, *w2tl;
    bf16 *Hkeh, *Hkel, *Hqeh, *Hqel, *VTh, *VTl;
    bf16 *Qch, *Qcl, *Kch, *Kcl, *KcTh, *KcTl, *SxTh, *SxTl, *Ph, *Pl, *rnh, *rnl;
    float *pk, *pq, *amp, *G, *ret;
    cudaGetSymbolAddress((void**)&xhi, g_xhi);   cudaGetSymbolAddress((void**)&xlo, g_xlo);
    cudaGetSymbolAddress((void**)&w1th, g_w1th); cudaGetSymbolAddress((void**)&w1tl, g_w1tl);
    cudaGetSymbolAddress((void**)&owth, g_owth); cudaGetSymbolAddress((void**)&owtl, g_owtl);
    cudaGetSymbolAddress((void**)&w2th, g_w2th); cudaGetSymbolAddress((void**)&w2tl, g_w2tl);
    cudaGetSymbolAddress((void**)&Hkeh, g_Hkeh); cudaGetSymbolAddress((void**)&Hkel, g_Hkel);
    cudaGetSymbolAddress((void**)&Hqeh, g_Hqeh); cudaGetSymbolAddress((void**)&Hqel, g_Hqel);
    cudaGetSymbolAddress((void**)&VTh, g_VTh);   cudaGetSymbolAddress((void**)&VTl, g_VTl);
    cudaGetSymbolAddress((void**)&Qch, g_Qch);   cudaGetSymbolAddress((void**)&Qcl, g_Qcl);
    cudaGetSymbolAddress((void**)&Kch, g_Kch);   cudaGetSymbolAddress((void**)&Kcl, g_Kcl);
    cudaGetSymbolAddress((void**)&KcTh, g_KcTh); cudaGetSymbolAddress((void**)&KcTl, g_KcTl);
    cudaGetSymbolAddress((void**)&SxTh, g_SxTh); cudaGetSymbolAddress((void**)&SxTl, g_SxTl);
    cudaGetSymbolAddress((void**)&Ph, g_Ph);     cudaGetSymbolAddress((void**)&Pl, g_Pl);
    cudaGetSymbolAddress((void**)&rnh, g_rnh);   cudaGetSymbolAddress((void**)&rnl, g_rnl);
    cudaGetSymbolAddress((void**)&pk, g_pk);     cudaGetSymbolAddress((void**)&pq, g_pq);
    cudaGetSymbolAddress((void**)&amp, g_amp);   cudaGetSymbolAddress((void**)&G, g_G);
    cudaGetSymbolAddress((void**)&ret, g_ret);

    const int SM128 = 81920, SM64 = 61440;
    cudaFuncSetAttribute(gemm_multi3<128,128>, cudaFuncAttributeMaxDynamicSharedMemorySize, SM128);
    cudaFuncSetAttribute(gemm_multi3<128,64>,  cudaFuncAttributeMaxDynamicSharedMemorySize, SM64);
    cudaFuncSetAttribute(gemm_chunk<128,128>,  cudaFuncAttributeMaxDynamicSharedMemorySize, SM128);

    // 0) input conversion + weight transpose/split
    convx_k<<<(LL * DD + 255) / 256, 256>>>(x);
    {
        WTJobs jb;
        jb.j[0] = { ke_w1, w1th,            w1tl,            DD, DD };
        jb.j[1] = { qe_w1, w1th + DD*DD,    w1tl + DD*DD,    DD, DD };
        jb.j[2] = { v_w,   w1th + 2*DD*DD,  w1tl + 2*DD*DD,  DD, DD };
        jb.j[3] = { out_w, owth,            owtl,            DD, DD };
        jb.j[4] = { ke_w2, w2th,            w2tl,            DD, KK };
        jb.j[5] = { qe_w2, w2th + KK*DD,    w2tl + KK*DD,    DD, KK };
        jb.j[6] = { amp_w, w2th + 2*KK*DD,  w2tl + 2*KK*DD,  DD, KK };
        wtrans_k<<<dim3(64, 1, 7), 256>>>(jb);
    }

    GArg z{}; // zero template

    // 1) fused big: Hke=gelu(x@ke_w1+b), Hqe=gelu(x@qe_w1+b), VT=(x@v_w+b)^T
    {
        GArg a0 = z, a1 = z, a2 = z;
        a0.Ahi = xhi; a0.Alo = xlo; a0.Bhi = w1th;           a0.Blo = w1tl;
        a0.bias = ke_b1; a0.epi = 1; a0.Chi = Hkeh; a0.Clo = Hkel; a0.ldh = DD;
        a1 = a0; a1.Bhi = w1th + DD*DD; a1.Blo = w1tl + DD*DD;
        a1.bias = qe_b1; a1.Chi = Hqeh; a1.Clo = Hqel;
        a2 = a0; a2.Bhi = w1th + 2*DD*DD; a2.Blo = w1tl + 2*DD*DD;
        a2.bias = v_b; a2.epi = 0; a2.Chi = VTh; a2.Clo = VTl; a2.transOut = 1; a2.ldh = LL;
        gemm_multi3<128,128><<<dim3(DD/128, LL/128, 3), 256, SM128>>>(
            a0, a1, a2, LL, DD, DD, DD, DD, DD);
    }

    // 2) fused narrow: pk, pq, amp (fp32 outputs)
    {
        GArg a0 = z, a1 = z, a2 = z;
        a0.Ahi = Hkeh; a0.Alo = Hkel; a0.Bhi = w2th; a0.Blo = w2tl;
        a0.bias = ke_b2; a0.epi = 2; a0.Cf = pk;
        a1 = a0; a1.Ahi = Hqeh; a1.Alo = Hqel; a1.Bhi = w2th + KK*DD; a1.Blo = w2tl + KK*DD;
        a1.bias = qe_b2; a1.Cf = pq;
        a2 = a0; a2.Ahi = xhi; a2.Alo = xlo; a2.Bhi = w2th + 2*KK*DD; a2.Blo = w2tl + 2*KK*DD;
        a2.bias = amp_b; a2.epi = 3; a2.Cf = amp;
        gemm_multi3<128,64><<<dim3(1, LL/128, 3), 256, SM64>>>(
            a0, a1, a2, LL, KK, DD, DD, DD, KK);
    }

    // 3) phasors
    phasor_k<<<(LL * KK + 255) / 256, 256>>>();

    // 4) G_c = KcT_c @ V_c   (M=2K=128, N=D, K=CH)
    {
        GArg a = z;
        a.Ahi = KcTh; a.Alo = KcTl; a.Bhi = VTh; a.Blo = VTl; a.Cf = G;
        gemm_chunk<128,128><<<dim3(DD/128, 1, NCH), 256, SM128>>>(
            a, CH, CH, (long)TWOK*DD, 0, TWOK, DD, CH, LL, LL, DD);
    }

    // 5) exclusive chunk scan -> SxT (hi/lo)
    scan_k<<<(TWOK * DD + 255) / 256, 256>>>();

    // 6) P_c = tril(Qc_c @ Kc_c^T)  -> hi/lo
    {
        GArg a = z;
        a.Ahi = Qch; a.Alo = Qcl; a.Bhi = Kch; a.Blo = Kcl;
        a.epi = 5; a.Chi = Ph; a.Clo = Pl; a.ldh = CH;
        gemm_chunk<128,128><<<dim3(1, 1, NCH), 256, SM128>>>(
            a, (long)CH*TWOK, (long)CH*TWOK, 0, (long)CH*CH,
            CH, CH, TWOK, TWOK, TWOK, CH);
    }

    // 7) ret_c = Qc_c @ Sx_c
    {
        GArg a = z;
        a.Ahi = Qch; a.Alo = Qcl; a.Bhi = SxTh; a.Blo = SxTl; a.Cf = ret;
        gemm_chunk<128,128><<<dim3(DD/128, 1, NCH), 256, SM128>>>(
            a, (long)CH*TWOK, (long)DD*TWOK, (long)CH*DD, 0,
            CH, DD, TWOK, TWOK, TWOK, DD);
    }

    // 8) ret_c = (ret_c + P_c @ V_c) * rsqrt((l+1)*K)
    {
        GArg a = z;
        a.Ahi = Ph; a.Alo = Pl; a.Bhi = VTh; a.Blo = VTl;
        a.Cin = ret; a.Cf = ret; a.epi = 6;
        gemm_chunk<128,128><<<dim3(DD/128, 1, NCH), 256, SM128>>>(
            a, (long)CH*CH, CH, (long)CH*DD, 0,
            CH, DD, CH, CH, LL, DD);
    }

    // 9) LayerNorm -> rn hi/lo
    ln_k<<<LL, 256>>>(ret, ln_g, ln_b);

    // 10) out = x + rn @ out_w + out_b
    {
        GArg a = z;
        a.Ahi = rnh; a.Alo = rnl; a.Bhi = owth; a.Blo = owtl;
        a.bias = out_b; a.X = x; a.epi = 4; a.Cf = out;
        gemm_multi3<128,128><<<dim3(DD/128, LL/128, 1), 256, SM128>>>(
            a, a, a, LL, DD, DD, DD, DD, DD);
    }

    (void)in_sizes; (void)n_in; (void)out_size;
}

// round 4
// speedup vs baseline: 1.5054x; 1.4566x over previous
#include <cuda_runtime.h>
#include <cuda_bf16.h>
#include <math.h>

#define LL   2048
#define DD   512
#define KK   64
#define TWOK 128
#define CH   128
#define NCH  16
#define PI_F 3.14159265358979323846f
#define NBLK 148
#define NTHR 256

typedef __nv_bfloat16 bf16;

// ------------------------------ buffers -----------------------------------
static __device__ bf16  g_xhi [LL*DD],      g_xlo [LL*DD];
static __device__ bf16  g_w1th[3*DD*DD],    g_w1tl[3*DD*DD];
static __device__ bf16  g_owth[DD*DD],      g_owtl[DD*DD];
static __device__ bf16  g_w2th[3*KK*DD],    g_w2tl[3*KK*DD];
static __device__ bf16  g_Hkeh[LL*DD],      g_Hkel[LL*DD];
static __device__ bf16  g_Hqeh[LL*DD],      g_Hqel[LL*DD];
static __device__ bf16  g_VTh [DD*LL],      g_VTl [DD*LL];
static __device__ float g_pk  [LL*KK], g_pq[LL*KK], g_amp[LL*KK];
static __device__ bf16  g_Qch [LL*TWOK],    g_Qcl [LL*TWOK];
static __device__ bf16  g_Kch [LL*TWOK],    g_Kcl [LL*TWOK];
static __device__ bf16  g_KcTh[TWOK*LL],    g_KcTl[TWOK*LL];
static __device__ float g_GT  [NCH*DD*TWOK];                 // [c][d][kk]
static __device__ bf16  g_SxTh[NCH*DD*TWOK],g_SxTl[NCH*DD*TWOK];
static __device__ bf16  g_Ph  [NCH*CH*CH],  g_Pl  [NCH*CH*CH];
static __device__ float g_ret [LL*DD];
static __device__ bf16  g_rnh [LL*DD],      g_rnl [LL*DD];

__device__ unsigned g_bar, g_gen;

// ------------------------------ grid barrier -------------------------------
__device__ __forceinline__ void grid_sync()
{
    __syncthreads();
    if (threadIdx.x == 0) {
        unsigned g = *(volatile unsigned*)&g_gen;   // read BEFORE arriving
        __threadfence();
        unsigned t = atomicAdd(&g_bar, 1u);
        if (t == NBLK - 1) {
            atomicExch(&g_bar, 0u);
            __threadfence();
            atomicAdd(&g_gen, 1u);
        } else {
            while (*(volatile unsigned*)&g_gen == g) { __nanosleep(32); }
        }
        __threadfence();
    }
    __syncthreads();
}

// ------------------------------ PTX helpers --------------------------------
__device__ __forceinline__ void ldmat4(unsigned& r0, unsigned& r1,
                                       unsigned& r2, unsigned& r3, unsigned addr)
{
    asm volatile("ldmatrix.sync.aligned.m8n8.x4.shared.b16 {%0,%1,%2,%3}, [%4];\n"
                 : "=r"(r0), "=r"(r1), "=r"(r2), "=r"(r3) : "r"(addr));
}
__device__ __forceinline__ void mma16816(float* c, const unsigned* a, const unsigned* b)
{
    asm volatile("mma.sync.aligned.m16n8k16.row.col.f32.bf16.bf16.f32 "
                 "{%0,%1,%2,%3}, {%4,%5,%6,%7}, {%8,%9}, {%0,%1,%2,%3};\n"
                 : "+f"(c[0]), "+f"(c[1]), "+f"(c[2]), "+f"(c[3])
                 : "r"(a[0]), "r"(a[1]), "r"(a[2]), "r"(a[3]), "r"(b[0]), "r"(b[1]));
}
__device__ __forceinline__ void cpasync16(unsigned dst, const void* src)
{
    asm volatile("cp.async.cg.shared.global [%0], [%1], 16;\n" :: "r"(dst), "l"(src));
}
__device__ __forceinline__ void split_store(bf16* hi, bf16* lo, size_t i, float v)
{
    bf16 h = __float2bfloat16_rn(v);
    hi[i] = h;
    lo[i] = __float2bfloat16_rn(v - __bfloat162float(h));
}

// ------------------------------ GEMM tile ----------------------------------
struct Epi {
    const float *bias, *X;
    float *Cf;
    bf16 *Chi, *Clo;
    int epi, transOut, ldh, ldc, mrow0;
};

// C(BMxBN tile at m0,n0) = epi( A1@B1^T [+ A2@B2^T] + bias ), 3-way bf16 split.
// B operands are (N rows, K cols) k-contiguous. 3-deep cp.async pipeline.
template<int BM, int BN>
__device__ void gemm_tile(char* smem, int m0, int n0,
    const bf16* A1h, const bf16* A1l, int lda1,
    const bf16* B1h, const bf16* B1l, int ldb1, int K1,
    const bf16* A2h, const bf16* A2l, int lda2,
    const bf16* B2h, const bf16* B2l, int ldb2, int K2,
    Epi e)
{
    constexpr int BK = 32, PK = 40;
    constexpr int ASZ = 2 * BM * PK, BSZ = 2 * BN * PK, BUF = ASZ + BSZ;
    bf16* sb = (bf16*)smem;
    const unsigned s0 = (unsigned)__cvta_generic_to_shared(sb);
    const int tid = threadIdx.x, lane = tid & 31, warp = tid >> 5;
    const int wm = (warp & 3) * (BM / 4), wn = (warp >> 2) * (BN / 2);
    constexpr int MT = (BM / 4) / 16, NT8 = (BN / 2) / 8;

    float c[MT][NT8][4];
#pragma unroll
    for (int i = 0; i < MT; i++)
#pragma unroll
        for (int j = 0; j < NT8; j++)
#pragma unroll
            for (int el = 0; el < 4; el++) c[i][j][el] = 0.f;

    auto issue = [&](int buf, int k0, const bf16* Ah, const bf16* Al, int lda,
                     const bf16* Bh, const bf16* Bl, int ldb) {
        const unsigned base = s0 + (unsigned)(buf * BUF * 2);
#pragma unroll
        for (int q = 0; q < (BM * 8) / NTHR; q++) {
            int idx = q * NTHR + tid, row = idx >> 3, sub = idx & 7;
            int s = sub >> 2, kc = sub & 3;
            const bf16* src = (s ? Al : Ah) + (size_t)(m0 + row) * lda + k0 + kc * 8;
            cpasync16(base + (unsigned)(((s * BM + row) * PK + kc * 8) * 2), src);
        }
#pragma unroll
        for (int q = 0; q < (BN * 8) / NTHR; q++) {
            int idx = q * NTHR + tid, row = idx >> 3, sub = idx & 7;
            int s = sub >> 2, kc = sub & 3;
            const bf16* src = (s ? Bl : Bh) + (size_t)(n0 + row) * ldb + k0 + kc * 8;
            cpasync16(base + (unsigned)((ASZ + (s * BN + row) * PK + kc * 8) * 2), src);
        }
        asm volatile("cp.async.commit_group;\n");
    };

    const int a_row = lane & 15, a_col = (lane >> 4) * 8;
    const int gq = lane >> 3, rr = lane & 7;
    const int b_row = ((gq >> 1) << 3) + rr, b_col = (gq & 1) * 8;

    auto compute = [&](int buf) {
        const unsigned aB = s0 + (unsigned)(buf * BUF * 2);
        const unsigned bB = aB + (unsigned)(ASZ * 2);
#pragma unroll
        for (int kk = 0; kk < 2; ++kk) {
            const int ks = kk * 16;
            unsigned af[2][MT][4];
#pragma unroll
            for (int s = 0; s < 2; s++)
#pragma unroll
                for (int mt = 0; mt < MT; mt++)
                    ldmat4(af[s][mt][0], af[s][mt][1], af[s][mt][2], af[s][mt][3],
                           aB + (unsigned)(((s * BM + wm + mt * 16 + a_row) * PK + ks + a_col) * 2));
            unsigned bfr[2][NT8][2];
#pragma unroll
            for (int s = 0; s < 2; s++)
#pragma unroll
                for (int p = 0; p < NT8 / 2; p++) {
                    unsigned r0, r1, r2, r3;
                    ldmat4(r0, r1, r2, r3,
                           bB + (unsigned)(((s * BN + wn + p * 16 + b_row) * PK + ks + b_col) * 2));
                    bfr[s][2 * p][0] = r0;  bfr[s][2 * p][1] = r1;
                    bfr[s][2 * p + 1][0] = r2;  bfr[s][2 * p + 1][1] = r3;
                }
#pragma unroll
            for (int mt = 0; mt < MT; mt++)
#pragma unroll
                for (int nt = 0; nt < NT8; nt++) {
                    mma16816(c[mt][nt], af[0][mt], bfr[0][nt]);
                    mma16816(c[mt][nt], af[0][mt], bfr[1][nt]);
                    mma16816(c[mt][nt], af[1][mt], bfr[0][nt]);
                }
        }
    };

    const int nk1 = K1 / BK, nk2 = K2 / BK, nk = nk1 + nk2;
    auto issue_t = [&](int t) {
        if (t < nk1) issue(t % 3, t * BK, A1h, A1l, lda1, B1h, B1l, ldb1);
        else         issue(t % 3, (t - nk1) * BK, A2h, A2l, lda2, B2h, B2l, ldb2);
    };

    issue_t(0);
    if (nk > 1) issue_t(1);
    for (int i = 0; i < nk; i++) {
        if (i + 2 < nk) issue_t(i + 2);
        int pend = nk - 1 - i; if (pend > 2) pend = 2;
        if (pend == 2)      asm volatile("cp.async.wait_group 2;\n");
        else if (pend == 1) asm volatile("cp.async.wait_group 1;\n");
        else                asm volatile("cp.async.wait_group 0;\n");
        __syncthreads();
        compute(i % 3);
        __syncthreads();
    }

    // epilogue
#pragma unroll
    for (int mt = 0; mt < MT; mt++)
#pragma unroll
        for (int nt = 0; nt < NT8; nt++)
#pragma unroll
            for (int el = 0; el < 4; el++) {
                int m = m0 + wm + mt * 16 + (lane >> 2) + ((el >> 1) << 3);
                int n = n0 + wn + nt * 8 + ((lane & 3) << 1) + (el & 1);
                float v = c[mt][nt][el];
                if (e.bias) v += e.bias[n];
                switch (e.epi) {
                    case 1: v = 0.5f * v * (1.f + erff(v * 0.70710678118654752f)); break;
                    case 2: v = tanhf(v) * PI_F; break;
                    case 3: v = (v > 20.f ? v : log1pf(expf(v))) + 0.1f; break;
                    case 4: v += e.X[(size_t)m * e.ldc + n]; break;
                    case 5: if (n > m) v = 0.f; break;
                    case 6: v *= rsqrtf((float)(e.mrow0 + m + 1) * (float)KK); break;
                }
                if (e.Cf) e.Cf[(size_t)m * e.ldc + n] = v;
                if (e.Chi) {
                    size_t oi = e.transOut ? ((size_t)n * e.ldh + m)
                                           : ((size_t)m * e.ldh + n);
                    split_store(e.Chi, e.Clo, oi, v);
                }
            }
}

// ------------------------------ megakernel ---------------------------------
struct MParams {
    const float *x, *ke_w1, *ke_b1, *ke_w2, *ke_b2, *qe_w1, *qe_b1, *qe_w2, *qe_b2,
                *amp_w, *amp_b, *v_w, *v_b, *ln_g, *ln_b, *out_w, *out_b;
    float* out;
};

__global__ __launch_bounds__(NTHR, 1) void mega(MParams p)
{
    extern __shared__ char smem[];
    __shared__ float sh[NTHR];
    const int bid = blockIdx.x, tid = threadIdx.x;
    const int gt = bid * NTHR + tid, GS = NBLK * NTHR;

    // ---- S0: convert x, transpose+split weights
    for (int i = gt; i < LL * DD; i += GS) split_store(g_xhi, g_xlo, i, p.x[i]);
    {
        const float* s4[4] = { p.ke_w1, p.qe_w1, p.v_w, p.out_w };
        bf16* dh[4] = { g_w1th, g_w1th + DD*DD, g_w1th + 2*DD*DD, g_owth };
        bf16* dl[4] = { g_w1tl, g_w1tl + DD*DD, g_w1tl + 2*DD*DD, g_owtl };
        for (int j = 0; j < 4; j++)
            for (int i = gt; i < DD * DD; i += GS) {
                int k = i / DD, n = i % DD;
                split_store(dh[j], dl[j], (size_t)n * DD + k, s4[j][i]);
            }
        const float* s2[3] = { p.ke_w2, p.qe_w2, p.amp_w };
        for (int j = 0; j < 3; j++)
            for (int i = gt; i < DD * KK; i += GS) {
                int k = i / KK, n = i % KK;
                split_store(g_w2th + (size_t)j*KK*DD, g_w2tl + (size_t)j*KK*DD,
                            (size_t)n * DD + k, s2[j][i]);
            }
    }
    grid_sync();

    // ---- S1: Hke/Hqe/VT  (192 tiles, BM=BN=128)
    for (int t = bid; t < 192; t += NBLK) {
        int z = t / 64, r = t % 64, m0 = (r >> 2) * 128, n0 = (r & 3) * 128;
        const bf16* Bh = g_w1th + (size_t)z * DD * DD;
        const bf16* Bl = g_w1tl + (size_t)z * DD * DD;
        Epi e{}; e.ldc = DD; e.ldh = DD;
        if (z == 0)      { e.bias = p.ke_b1; e.epi = 1; e.Chi = g_Hkeh; e.Clo = g_Hkel; }
        else if (z == 1) { e.bias = p.qe_b1; e.epi = 1; e.Chi = g_Hqeh; e.Clo = g_Hqel; }
        else             { e.bias = p.v_b;   e.epi = 0; e.Chi = g_VTh;  e.Clo = g_VTl;
                           e.transOut = 1; e.ldh = LL; }
        gemm_tile<128,128>(smem, m0, n0, g_xhi, g_xlo, DD, Bh, Bl, DD, DD,
                           nullptr, nullptr, 0, nullptr, nullptr, 0, 0, e);
    }
    grid_sync();

    // ---- S2: pk/pq/amp  (48 tiles, BN=64)
    for (int t = bid; t < 48; t += NBLK) {
        int z = t / 16, m0 = (t % 16) * 128;
        Epi e{}; e.ldc = KK;
        const bf16 *Ah, *Al;
        if (z == 0)      { Ah = g_Hkeh; Al = g_Hkel; e.bias = p.ke_b2; e.epi = 2; e.Cf = g_pk; }
        else if (z == 1) { Ah = g_Hqeh; Al = g_Hqel; e.bias = p.qe_b2; e.epi = 2; e.Cf = g_pq; }
        else             { Ah = g_xhi;  Al = g_xlo;  e.bias = p.amp_b; e.epi = 3; e.Cf = g_amp; }
        gemm_tile<128,64>(smem, m0, 0, Ah, Al, DD,
                          g_w2th + (size_t)z*KK*DD, g_w2tl + (size_t)z*KK*DD, DD, DD,
                          nullptr, nullptr, 0, nullptr, nullptr, 0, 0, e);
    }
    grid_sync();

    // ---- S3: phasors
    for (int i = gt; i < LL * KK; i += GS) {
        int l = i / KK, k = i % KK;
        float a = g_amp[i], s, cc;
        sincosf(g_pk[i], &s, &cc);
        float kr = a * cc, ki = a * s;
        split_store(g_Kch,  g_Kcl,  (size_t)l * TWOK + k,      kr);
        split_store(g_Kch,  g_Kcl,  (size_t)l * TWOK + KK + k, ki);
        split_store(g_KcTh, g_KcTl, (size_t)k * LL + l,        kr);
        split_store(g_KcTh, g_KcTl, (size_t)(k + KK) * LL + l, ki);
        sincosf(g_pq[i], &s, &cc);
        split_store(g_Qch, g_Qcl, (size_t)l * TWOK + k,      a * cc);
        split_store(g_Qch, g_Qcl, (size_t)l * TWOK + KK + k, a * s);
    }
    grid_sync();

    // ---- S4: GT = VT@KcT^T (128 tiles) + P = tril(Q@Kc^T) (32 tiles), BN=64
    for (int t = bid; t < 160; t += NBLK) {
        if (t < 128) {
            int z = t >> 3, r = t & 7, m0 = (r >> 1) * 128, n0 = (r & 1) * 64;
            Epi e{}; e.ldc = TWOK; e.epi = 0; e.Cf = g_GT + (size_t)z * DD * TWOK;
            gemm_tile<128,64>(smem, m0, n0,
                g_VTh + (size_t)z * CH,  g_VTl + (size_t)z * CH,  LL,
                g_KcTh + (size_t)z * CH, g_KcTl + (size_t)z * CH, LL, CH,
                nullptr, nullptr, 0, nullptr, nullptr, 0, 0, e);
        } else {
            int u = t - 128, z = u >> 1, n0 = (u & 1) * 64;
            Epi e{}; e.ldc = CH; e.ldh = CH; e.epi = 5;
            e.Chi = g_Ph + (size_t)z * CH * CH; e.Clo = g_Pl + (size_t)z * CH * CH;
            gemm_tile<128,64>(smem, 0, n0,
                g_Qch + (size_t)z * CH * TWOK, g_Qcl + (size_t)z * CH * TWOK, TWOK,
                g_Kch + (size_t)z * CH * TWOK, g_Kcl + (size_t)z * CH * TWOK, TWOK, TWOK,
                nullptr, nullptr, 0, nullptr, nullptr, 0, 0, e);
        }
    }
    grid_sync();

    // ---- S5: exclusive chunk scan (fully coalesced, [c][d][kk] layout)
    for (int i = gt; i < TWOK * DD; i += GS) {
        float run = 0.f;
#pragma unroll
        for (int cch = 0; cch < NCH; cch++) {
            split_store(g_SxTh, g_SxTl, (size_t)cch * DD * TWOK + i, run);
            run += g_GT[(size_t)cch * DD * TWOK + i];
        }
    }
    grid_sync();

    // ---- S6: ret = (Q@Sx + P@V) * rsqrt((l+1)K)  (128 tiles, fused 2-phase)
    for (int t = bid; t < 128; t += NBLK) {
        int z = t >> 3, n0 = (t & 7) * 64;
        Epi e{}; e.ldc = DD; e.epi = 6; e.mrow0 = z * CH;
        e.Cf = g_ret + (size_t)z * CH * DD;
        gemm_tile<128,64>(smem, 0, n0,
            g_Qch  + (size_t)z * CH * TWOK, g_Qcl  + (size_t)z * CH * TWOK, TWOK,
            g_SxTh + (size_t)z * DD * TWOK, g_SxTl + (size_t)z * DD * TWOK, TWOK, TWOK,
            g_Ph   + (size_t)z * CH * CH,   g_Pl   + (size_t)z * CH * CH,   CH,
            g_VTh  + (size_t)z * CH,        g_VTl  + (size_t)z * CH,        LL, CH,
            e);
    }
    grid_sync();

    // ---- S7: LayerNorm
    for (int row = bid; row < LL; row += NBLK) {
        const float* r = g_ret + (size_t)row * DD;
        float v0 = r[tid], v1 = r[tid + NTHR];
        sh[tid] = v0 + v1;
        __syncthreads();
#pragma unroll
        for (int o = 128; o > 0; o >>= 1) { if (tid < o) sh[tid] += sh[tid + o]; __syncthreads(); }
        float mu = sh[0] * (1.f / DD);
        __syncthreads();
        float d0 = v0 - mu, d1 = v1 - mu;
        sh[tid] = d0 * d0 + d1 * d1;
        __syncthreads();
#pragma unroll
        for (int o = 128; o > 0; o >>= 1) { if (tid < o) sh[tid] += sh[tid + o]; __syncthreads(); }
        float inv = rsqrtf(sh[0] * (1.f / DD) + 1e-5f);
        __syncthreads();
        split_store(g_rnh, g_rnl, (size_t)row * DD + tid,
                    d0 * inv * p.ln_g[tid] + p.ln_b[tid]);
        split_store(g_rnh, g_rnl, (size_t)row * DD + tid + NTHR,
                    d1 * inv * p.ln_g[tid + NTHR] + p.ln_b[tid + NTHR]);
    }
    grid_sync();

    // ---- S8: out = x + rn @ out_w + out_b  (128 tiles, BN=64)
    for (int t = bid; t < 128; t += NBLK) {
        int m0 = (t >> 3) * 128, n0 = (t & 7) * 64;
        Epi e{}; e.ldc = DD; e.epi = 4; e.X = p.x; e.bias = p.out_b; e.Cf = p.out;
        gemm_tile<128,64>(smem, m0, n0, g_rnh, g_rnl, DD, g_owth, g_owtl, DD, DD,
                          nullptr, nullptr, 0, nullptr, nullptr, 0, 0, e);
    }
}

// ------------------------------ host ---------------------------------------
extern "C" void kernel_launch(void* const* d_in, const int* in_sizes, int n_in,
                              void* d_out, int out_size)
{
    MParams p;
    p.x     = (const float*)d_in[0];
    p.ke_w1 = (const float*)d_in[1];   p.ke_b1 = (const float*)d_in[2];
    p.ke_w2 = (const float*)d_in[3];   p.ke_b2 = (const float*)d_in[4];
    p.qe_w1 = (const float*)d_in[5];   p.qe_b1 = (const float*)d_in[6];
    p.qe_w2 = (const float*)d_in[7];   p.qe_b2 = (const float*)d_in[8];
    p.amp_w = (const float*)d_in[9];   p.amp_b = (const float*)d_in[10];
    p.v_w   = (const float*)d_in[11];  p.v_b   = (const float*)d_in[12];
    p.ln_g  = (const float*)d_in[13];  p.ln_b  = (const float*)d_in[14];
    p.out_w = (const float*)d_in[15];  p.out_b = (const float*)d_in[16];
    p.out   = (float*)d_out;

    const int SMEM = 3 * (2 * 128 * 40 + 2 * 128 * 40) * 2;   // 122880 B
    cudaFuncSetAttribute(mega, cudaFuncAttributeMaxDynamicSharedMemorySize, SMEM);
    mega<<<NBLK, NTHR, SMEM>>>(p);

    (void)in_sizes; (void)n_in; (void)out_size;
}

// round 5
// speedup vs baseline: 1.8291x; 1.2150x over previous
#include <cuda_runtime.h>
#include <cuda_bf16.h>
#include <math.h>

#define LL   2048
#define DD   512
#define KK   64
#define TWOK 128
#define CH   128
#define NCH  16
#define PI_F 3.14159265358979323846f
#define NBLK 296
#define NTHR 256

typedef __nv_bfloat16 bf16;

// ------------------------------ buffers -----------------------------------
static __device__ bf16  g_xhi [LL*DD],      g_xlo [LL*DD];
static __device__ bf16  g_w1th[3*DD*DD],    g_w1tl[3*DD*DD];
static __device__ bf16  g_owth[DD*DD],      g_owtl[DD*DD];
static __device__ bf16  g_w2th[3*KK*DD],    g_w2tl[3*KK*DD];
static __device__ bf16  g_Hkeh[LL*DD],      g_Hkel[LL*DD];
static __device__ bf16  g_Hqeh[LL*DD],      g_Hqel[LL*DD];
static __device__ bf16  g_VTh [DD*LL],      g_VTl [DD*LL];
static __device__ float g_pk  [LL*KK], g_pq[LL*KK], g_amp[LL*KK];
static __device__ bf16  g_Qch [LL*TWOK],    g_Qcl [LL*TWOK];
static __device__ bf16  g_Kch [LL*TWOK],    g_Kcl [LL*TWOK];
static __device__ bf16  g_KcTh[TWOK*LL],    g_KcTl[TWOK*LL];
static __device__ float g_GT  [NCH*DD*TWOK];                 // [c][d][kk]
static __device__ bf16  g_SxTh[NCH*DD*TWOK],g_SxTl[NCH*DD*TWOK];
static __device__ bf16  g_Ph  [NCH*CH*CH],  g_Pl  [NCH*CH*CH];
static __device__ float g_ret [LL*DD];
static __device__ bf16  g_rnh [LL*DD],      g_rnl [LL*DD];

__device__ unsigned g_bar, g_gen;

// ------------------------------ grid barrier -------------------------------
__device__ __forceinline__ void grid_sync()
{
    __syncthreads();
    if (threadIdx.x == 0) {
        unsigned g = *(volatile unsigned*)&g_gen;   // read BEFORE arriving
        __threadfence();
        unsigned t = atomicAdd(&g_bar, 1u);
        if (t == NBLK - 1) {
            atomicExch(&g_bar, 0u);
            __threadfence();
            atomicAdd(&g_gen, 1u);
        } else {
            while (*(volatile unsigned*)&g_gen == g) { __nanosleep(32); }
        }
        __threadfence();
    }
    __syncthreads();
}

// ------------------------------ PTX helpers --------------------------------
__device__ __forceinline__ void ldmat4(unsigned& r0, unsigned& r1,
                                       unsigned& r2, unsigned& r3, unsigned addr)
{
    asm volatile("ldmatrix.sync.aligned.m8n8.x4.shared.b16 {%0,%1,%2,%3}, [%4];\n"
                 : "=r"(r0), "=r"(r1), "=r"(r2), "=r"(r3) : "r"(addr));
}
__device__ __forceinline__ void mma16816(float* c, const unsigned* a, const unsigned* b)
{
    asm volatile("mma.sync.aligned.m16n8k16.row.col.f32.bf16.bf16.f32 "
                 "{%0,%1,%2,%3}, {%4,%5,%6,%7}, {%8,%9}, {%0,%1,%2,%3};\n"
                 : "+f"(c[0]), "+f"(c[1]), "+f"(c[2]), "+f"(c[3])
                 : "r"(a[0]), "r"(a[1]), "r"(a[2]), "r"(a[3]), "r"(b[0]), "r"(b[1]));
}
__device__ __forceinline__ void cpasync16(unsigned dst, const void* src)
{
    asm volatile("cp.async.cg.shared.global [%0], [%1], 16;\n" :: "r"(dst), "l"(src));
}
__device__ __forceinline__ void split_store(bf16* hi, bf16* lo, size_t i, float v)
{
    bf16 h = __float2bfloat16_rn(v);
    hi[i] = h;
    lo[i] = __float2bfloat16_rn(v - __bfloat162float(h));
}

// ------------------------------ GEMM tile ----------------------------------
struct Epi {
    const float *bias, *X;
    float *Cf;
    bf16 *Chi, *Clo;
    int epi, transOut, ldh, ldc, mrow0;
};

// C(128x64 tile at m0,n0) = epi( A1@B1^T [+ A2@B2^T] + bias ), 3-way bf16 split.
// B operands are (N rows, K cols) k-contiguous. 3-deep cp.async pipeline,
// ONE __syncthreads per K-iteration (issue reordered after the barrier).
__device__ void gemm_tile(char* smem, int m0, int n0,
    const bf16* A1h, const bf16* A1l, int lda1,
    const bf16* B1h, const bf16* B1l, int ldb1, int K1,
    const bf16* A2h, const bf16* A2l, int lda2,
    const bf16* B2h, const bf16* B2l, int ldb2, int K2,
    Epi e)
{
    constexpr int BM = 128, BN = 64;
    constexpr int BK = 32, PK = 40;
    constexpr int ASZ = 2 * BM * PK, BSZ = 2 * BN * PK, BUF = ASZ + BSZ;
    bf16* sb = (bf16*)smem;
    const unsigned s0 = (unsigned)__cvta_generic_to_shared(sb);
    const int tid = threadIdx.x, lane = tid & 31, warp = tid >> 5;
    const int wm = (warp & 3) * (BM / 4), wn = (warp >> 2) * (BN / 2);
    constexpr int MT = 2, NT8 = 4;

    float c[MT][NT8][4];
#pragma unroll
    for (int i = 0; i < MT; i++)
#pragma unroll
        for (int j = 0; j < NT8; j++)
#pragma unroll
            for (int el = 0; el < 4; el++) c[i][j][el] = 0.f;

    auto issue = [&](int buf, int k0, const bf16* Ah, const bf16* Al, int lda,
                     const bf16* Bh, const bf16* Bl, int ldb) {
        const unsigned base = s0 + (unsigned)(buf * BUF * 2);
#pragma unroll
        for (int q = 0; q < (BM * 8) / NTHR; q++) {
            int idx = q * NTHR + tid, row = idx >> 3, sub = idx & 7;
            int s = sub >> 2, kc = sub & 3;
            const bf16* src = (s ? Al : Ah) + (size_t)(m0 + row) * lda + k0 + kc * 8;
            cpasync16(base + (unsigned)(((s * BM + row) * PK + kc * 8) * 2), src);
        }
#pragma unroll
        for (int q = 0; q < (BN * 8) / NTHR; q++) {
            int idx = q * NTHR + tid, row = idx >> 3, sub = idx & 7;
            int s = sub >> 2, kc = sub & 3;
            const bf16* src = (s ? Bl : Bh) + (size_t)(n0 + row) * ldb + k0 + kc * 8;
            cpasync16(base + (unsigned)((ASZ + (s * BN + row) * PK + kc * 8) * 2), src);
        }
        asm volatile("cp.async.commit_group;\n");
    };

    const int a_row = lane & 15, a_col = (lane >> 4) * 8;
    const int gq = lane >> 3, rr = lane & 7;
    const int b_row = ((gq >> 1) << 3) + rr, b_col = (gq & 1) * 8;

    auto compute = [&](int buf) {
        const unsigned aB = s0 + (unsigned)(buf * BUF * 2);
        const unsigned bB = aB + (unsigned)(ASZ * 2);
#pragma unroll
        for (int kk = 0; kk < 2; ++kk) {
            const int ks = kk * 16;
            unsigned af[2][MT][4];
#pragma unroll
            for (int s = 0; s < 2; s++)
#pragma unroll
                for (int mt = 0; mt < MT; mt++)
                    ldmat4(af[s][mt][0], af[s][mt][1], af[s][mt][2], af[s][mt][3],
                           aB + (unsigned)(((s * BM + wm + mt * 16 + a_row) * PK + ks + a_col) * 2));
            unsigned bfr[2][NT8][2];
#pragma unroll
            for (int s = 0; s < 2; s++)
#pragma unroll
                for (int p = 0; p < NT8 / 2; p++) {
                    unsigned r0, r1, r2, r3;
                    ldmat4(r0, r1, r2, r3,
                           bB + (unsigned)(((s * BN + wn + p * 16 + b_row) * PK + ks + b_col) * 2));
                    bfr[s][2 * p][0] = r0;  bfr[s][2 * p][1] = r1;
                    bfr[s][2 * p + 1][0] = r2;  bfr[s][2 * p + 1][1] = r3;
                }
#pragma unroll
            for (int mt = 0; mt < MT; mt++)
#pragma unroll
                for (int nt = 0; nt < NT8; nt++) {
                    mma16816(c[mt][nt], af[0][mt], bfr[0][nt]);
                    mma16816(c[mt][nt], af[0][mt], bfr[1][nt]);
                    mma16816(c[mt][nt], af[1][mt], bfr[0][nt]);
                }
        }
    };

    const int nk1 = K1 / BK, nk2 = K2 / BK, nk = nk1 + nk2;
    auto issue_t = [&](int t) {
        if (t < nk1) issue(t % 3, t * BK, A1h, A1l, lda1, B1h, B1l, ldb1);
        else         issue(t % 3, (t - nk1) * BK, A2h, A2l, lda2, B2h, B2l, ldb2);
    };

    issue_t(0);
    if (nk > 1) issue_t(1);
    for (int i = 0; i < nk; i++) {
        if (i + 1 < nk) asm volatile("cp.async.wait_group 1;\n");
        else            asm volatile("cp.async.wait_group 0;\n");
        __syncthreads();
        if (i + 2 < nk) issue_t(i + 2);
        compute(i % 3);
    }
    __syncthreads();   // protect smem before next tile reuses it

    // epilogue
#pragma unroll
    for (int mt = 0; mt < MT; mt++)
#pragma unroll
        for (int nt = 0; nt < NT8; nt++)
#pragma unroll
            for (int el = 0; el < 4; el++) {
                int m = m0 + wm + mt * 16 + (lane >> 2) + ((el >> 1) << 3);
                int n = n0 + wn + nt * 8 + ((lane & 3) << 1) + (el & 1);
                float v = c[mt][nt][el];
                if (e.bias) v += e.bias[n];
                switch (e.epi) {
                    case 1: v = 0.5f * v * (1.f + erff(v * 0.70710678118654752f)); break;
                    case 2: v = tanhf(v) * PI_F; break;
                    case 3: v = (v > 20.f ? v : log1pf(expf(v))) + 0.1f; break;
                    case 4: v += e.X[(size_t)m * e.ldc + n]; break;
                    case 5: if (n > m) v = 0.f; break;
                    case 6: v *= rsqrtf((float)(e.mrow0 + m + 1) * (float)KK); break;
                }
                if (e.Cf) e.Cf[(size_t)m * e.ldc + n] = v;
                if (e.Chi) {
                    size_t oi = e.transOut ? ((size_t)n * e.ldh + m)
                                           : ((size_t)m * e.ldh + n);
                    split_store(e.Chi, e.Clo, oi, v);
                }
            }
}

// ------------------------------ megakernel ---------------------------------
struct MParams {
    const float *x, *ke_w1, *ke_b1, *ke_w2, *ke_b2, *qe_w1, *qe_b1, *qe_w2, *qe_b2,
                *amp_w, *amp_b, *v_w, *v_b, *ln_g, *ln_b, *out_w, *out_b;
    float* out;
};

__global__ __launch_bounds__(NTHR, 2) void mega(MParams p)
{
    extern __shared__ char smem[];
    __shared__ float sh[NTHR];
    const int bid = blockIdx.x, tid = threadIdx.x;
    const int gt = bid * NTHR + tid, GS = NBLK * NTHR;

    // ---- S0: convert x, transpose+split weights
    for (int i = gt; i < LL * DD; i += GS) split_store(g_xhi, g_xlo, i, p.x[i]);
    {
        const float* s4[4] = { p.ke_w1, p.qe_w1, p.v_w, p.out_w };
        bf16* dh[4] = { g_w1th, g_w1th + DD*DD, g_w1th + 2*DD*DD, g_owth };
        bf16* dl[4] = { g_w1tl, g_w1tl + DD*DD, g_w1tl + 2*DD*DD, g_owtl };
        for (int j = 0; j < 4; j++)
            for (int i = gt; i < DD * DD; i += GS) {
                int k = i / DD, n = i % DD;
                split_store(dh[j], dl[j], (size_t)n * DD + k, s4[j][i]);
            }
        const float* s2[3] = { p.ke_w2, p.qe_w2, p.amp_w };
        for (int j = 0; j < 3; j++)
            for (int i = gt; i < DD * KK; i += GS) {
                int k = i / KK, n = i % KK;
                split_store(g_w2th + (size_t)j*KK*DD, g_w2tl + (size_t)j*KK*DD,
                            (size_t)n * DD + k, s2[j][i]);
            }
    }
    grid_sync();

    // ---- S1: Hke/Hqe/VT  (3 x 16 x 8 = 384 tiles, BN=64)
    for (int t = bid; t < 384; t += NBLK) {
        int z = t / 128, r = t % 128, m0 = (r >> 3) * 128, n0 = (r & 7) * 64;
        const bf16* Bh = g_w1th + (size_t)z * DD * DD;
        const bf16* Bl = g_w1tl + (size_t)z * DD * DD;
        Epi e{}; e.ldc = DD; e.ldh = DD;
        if (z == 0)      { e.bias = p.ke_b1; e.epi = 1; e.Chi = g_Hkeh; e.Clo = g_Hkel; }
        else if (z == 1) { e.bias = p.qe_b1; e.epi = 1; e.Chi = g_Hqeh; e.Clo = g_Hqel; }
        else             { e.bias = p.v_b;   e.epi = 0; e.Chi = g_VTh;  e.Clo = g_VTl;
                           e.transOut = 1; e.ldh = LL; }
        gemm_tile(smem, m0, n0, g_xhi, g_xlo, DD, Bh, Bl, DD, DD,
                  nullptr, nullptr, 0, nullptr, nullptr, 0, 0, e);
    }
    grid_sync();

    // ---- S2: pk/pq/amp  (48 tiles)
    for (int t = bid; t < 48; t += NBLK) {
        int z = t / 16, m0 = (t % 16) * 128;
        Epi e{}; e.ldc = KK;
        const bf16 *Ah, *Al;
        if (z == 0)      { Ah = g_Hkeh; Al = g_Hkel; e.bias = p.ke_b2; e.epi = 2; e.Cf = g_pk; }
        else if (z == 1) { Ah = g_Hqeh; Al = g_Hqel; e.bias = p.qe_b2; e.epi = 2; e.Cf = g_pq; }
        else             { Ah = g_xhi;  Al = g_xlo;  e.bias = p.amp_b; e.epi = 3; e.Cf = g_amp; }
        gemm_tile(smem, m0, 0, Ah, Al, DD,
                  g_w2th + (size_t)z*KK*DD, g_w2tl + (size_t)z*KK*DD, DD, DD,
                  nullptr, nullptr, 0, nullptr, nullptr, 0, 0, e);
    }
    grid_sync();

    // ---- S3: phasors
    for (int i = gt; i < LL * KK; i += GS) {
        int l = i / KK, k = i % KK;
        float a = g_amp[i], s, cc;
        sincosf(g_pk[i], &s, &cc);
        float kr = a * cc, ki = a * s;
        split_store(g_Kch,  g_Kcl,  (size_t)l * TWOK + k,      kr);
        split_store(g_Kch,  g_Kcl,  (size_t)l * TWOK + KK + k, ki);
        split_store(g_KcTh, g_KcTl, (size_t)k * LL + l,        kr);
        split_store(g_KcTh, g_KcTl, (size_t)(k + KK) * LL + l, ki);
        sincosf(g_pq[i], &s, &cc);
        split_store(g_Qch, g_Qcl, (size_t)l * TWOK + k,      a * cc);
        split_store(g_Qch, g_Qcl, (size_t)l * TWOK + KK + k, a * s);
    }
    grid_sync();

    // ---- S4: GT = VT@KcT^T (128 tiles) + P = tril(Q@Kc^T) (32 tiles)
    for (int t = bid; t < 160; t += NBLK) {
        if (t < 128) {
            int z = t >> 3, r = t & 7, m0 = (r >> 1) * 128, n0 = (r & 1) * 64;
            Epi e{}; e.ldc = TWOK; e.epi = 0; e.Cf = g_GT + (size_t)z * DD * TWOK;
            gemm_tile(smem, m0, n0,
                g_VTh + (size_t)z * CH,  g_VTl + (size_t)z * CH,  LL,
                g_KcTh + (size_t)z * CH, g_KcTl + (size_t)z * CH, LL, CH,
                nullptr, nullptr, 0, nullptr, nullptr, 0, 0, e);
        } else {
            int u = t - 128, z = u >> 1, n0 = (u & 1) * 64;
            Epi e{}; e.ldc = CH; e.ldh = CH; e.epi = 5;
            e.Chi = g_Ph + (size_t)z * CH * CH; e.Clo = g_Pl + (size_t)z * CH * CH;
            gemm_tile(smem, 0, n0,
                g_Qch + (size_t)z * CH * TWOK, g_Qcl + (size_t)z * CH * TWOK, TWOK,
                g_Kch + (size_t)z * CH * TWOK, g_Kcl + (size_t)z * CH * TWOK, TWOK, TWOK,
                nullptr, nullptr, 0, nullptr, nullptr, 0, 0, e);
        }
    }
    grid_sync();

    // ---- S5: exclusive chunk scan (coalesced, [c][d][kk] layout)
    for (int i = gt; i < TWOK * DD; i += GS) {
        float run = 0.f;
#pragma unroll
        for (int cch = 0; cch < NCH; cch++) {
            split_store(g_SxTh, g_SxTl, (size_t)cch * DD * TWOK + i, run);
            run += g_GT[(size_t)cch * DD * TWOK + i];
        }
    }
    grid_sync();

    // ---- S6: ret = (Q@Sx + P@V) * rsqrt((l+1)K)  (128 tiles, fused 2-phase)
    for (int t = bid; t < 128; t += NBLK) {
        int z = t >> 3, n0 = (t & 7) * 64;
        Epi e{}; e.ldc = DD; e.epi = 6; e.mrow0 = z * CH;
        e.Cf = g_ret + (size_t)z * CH * DD;
        gemm_tile(smem, 0, n0,
            g_Qch  + (size_t)z * CH * TWOK, g_Qcl  + (size_t)z * CH * TWOK, TWOK,
            g_SxTh + (size_t)z * DD * TWOK, g_SxTl + (size_t)z * DD * TWOK, TWOK, TWOK,
            g_Ph   + (size_t)z * CH * CH,   g_Pl   + (size_t)z * CH * CH,   CH,
            g_VTh  + (size_t)z * CH,        g_VTl  + (size_t)z * CH,        LL, CH,
            e);
    }
    grid_sync();

    // ---- S7: LayerNorm
    for (int row = bid; row < LL; row += NBLK) {
        const float* r = g_ret + (size_t)row * DD;
        float v0 = r[tid], v1 = r[tid + NTHR];
        sh[tid] = v0 + v1;
        __syncthreads();
#pragma unroll
        for (int o = 128; o > 0; o >>= 1) { if (tid < o) sh[tid] += sh[tid + o]; __syncthreads(); }
        float mu = sh[0] * (1.f / DD);
        __syncthreads();
        float d0 = v0 - mu, d1 = v1 - mu;
        sh[tid] = d0 * d0 + d1 * d1;
        __syncthreads();
#pragma unroll
        for (int o = 128; o > 0; o >>= 1) { if (tid < o) sh[tid] += sh[tid + o]; __syncthreads(); }
        float inv = rsqrtf(sh[0] * (1.f / DD) + 1e-5f);
        __syncthreads();
        split_store(g_rnh, g_rnl, (size_t)row * DD + tid,
                    d0 * inv * p.ln_g[tid] + p.ln_b[tid]);
        split_store(g_rnh, g_rnl, (size_t)row * DD + tid + NTHR,
                    d1 * inv * p.ln_g[tid + NTHR] + p.ln_b[tid + NTHR]);
    }
    grid_sync();

    // ---- S8: out = x + rn @ out_w + out_b  (128 tiles)
    for (int t = bid; t < 128; t += NBLK) {
        int m0 = (t >> 3) * 128, n0 = (t & 7) * 64;
        Epi e{}; e.ldc = DD; e.epi = 4; e.X = p.x; e.bias = p.out_b; e.Cf = p.out;
        gemm_tile(smem, m0, n0, g_rnh, g_rnl, DD, g_owth, g_owtl, DD, DD,
                  nullptr, nullptr, 0, nullptr, nullptr, 0, 0, e);
    }
}

// ------------------------------ host ---------------------------------------
extern "C" void kernel_launch(void* const* d_in, const int* in_sizes, int n_in,
                              void* d_out, int out_size)
{
    MParams p;
    p.x     = (const float*)d_in[0];
    p.ke_w1 = (const float*)d_in[1];   p.ke_b1 = (const float*)d_in[2];
    p.ke_w2 = (const float*)d_in[3];   p.ke_b2 = (const float*)d_in[4];
    p.qe_w1 = (const float*)d_in[5];   p.qe_b1 = (const float*)d_in[6];
    p.qe_w2 = (const float*)d_in[7];   p.qe_b2 = (const float*)d_in[8];
    p.amp_w = (const float*)d_in[9];   p.amp_b = (const float*)d_in[10];
    p.v_w   = (const float*)d_in[11];  p.v_b   = (const float*)d_in[12];
    p.ln_g  = (const float*)d_in[13];  p.ln_b  = (const float*)d_in[14];
    p.out_w = (const float*)d_in[15];  p.out_b = (const float*)d_in[16];
    p.out   = (float*)d_out;

    // 3 buffers x (A: 2*128*40 + B: 2*64*40) bf16 = 92160 bytes
    const int SMEM = 3 * (2 * 128 * 40 + 2 * 64 * 40) * 2;
    cudaFuncSetAttribute(mega, cudaFuncAttributeMaxDynamicSharedMemorySize, SMEM);
    mega<<<NBLK, NTHR, SMEM>>>(p);

    (void)in_sizes; (void)n_in; (void)out_size;
}

// round 6
// speedup vs baseline: 2.1447x; 1.1726x over previous
#include <cuda_runtime.h>
#include <cuda_bf16.h>
#include <math.h>

#define LL   2048
#define DD   512
#define KK   64
#define TWOK 128
#define CH   128
#define NCH  16
#define PI_F 3.14159265358979323846f
#define NBLK 296
#define NTHR 256

typedef __nv_bfloat16 bf16;

// ------------------------------ buffers -----------------------------------
static __device__ bf16  g_xhi [LL*DD],      g_xlo [LL*DD];
static __device__ bf16  g_w1th[3*DD*DD],    g_w1tl[3*DD*DD];
static __device__ bf16  g_owth[DD*DD],      g_owtl[DD*DD];
static __device__ bf16  g_w2th[3*KK*DD],    g_w2tl[3*KK*DD];
static __device__ bf16  g_Hkeh[LL*DD],      g_Hkel[LL*DD];
static __device__ bf16  g_Hqeh[LL*DD],      g_Hqel[LL*DD];
static __device__ bf16  g_VTh [DD*LL],      g_VTl [DD*LL];
static __device__ float g_pk  [LL*KK], g_pq[LL*KK], g_amp[LL*KK];
static __device__ bf16  g_Qch [LL*TWOK],    g_Qcl [LL*TWOK];
static __device__ bf16  g_Kch [LL*TWOK],    g_Kcl [LL*TWOK];
static __device__ bf16  g_KcTh[TWOK*LL],    g_KcTl[TWOK*LL];
static __device__ float g_GT  [NCH*DD*TWOK];                 // [c][d][kk]
static __device__ bf16  g_SxTh[NCH*DD*TWOK],g_SxTl[NCH*DD*TWOK];
static __device__ bf16  g_Ph  [NCH*CH*CH],  g_Pl  [NCH*CH*CH];
static __device__ float g_ret [LL*DD];
static __device__ bf16  g_rnh [LL*DD],      g_rnl [LL*DD];

__device__ unsigned g_bar, g_gen;

// ------------------------------ grid barrier -------------------------------
__device__ __forceinline__ void grid_sync()
{
    __syncthreads();
    if (threadIdx.x == 0) {
        unsigned g = *(volatile unsigned*)&g_gen;
        __threadfence();
        unsigned t = atomicAdd(&g_bar, 1u);
        if (t == NBLK - 1) {
            atomicExch(&g_bar, 0u);
            __threadfence();
            atomicAdd(&g_gen, 1u);
        } else {
            while (*(volatile unsigned*)&g_gen == g) { __nanosleep(32); }
        }
        __threadfence();
    }
    __syncthreads();
}

// ------------------------------ PTX helpers --------------------------------
__device__ __forceinline__ void ldmat4(unsigned& r0, unsigned& r1,
                                       unsigned& r2, unsigned& r3, unsigned addr)
{
    asm volatile("ldmatrix.sync.aligned.m8n8.x4.shared.b16 {%0,%1,%2,%3}, [%4];\n"
                 : "=r"(r0), "=r"(r1), "=r"(r2), "=r"(r3) : "r"(addr));
}
__device__ __forceinline__ void mma16816(float* c, const unsigned* a, const unsigned* b)
{
    asm volatile("mma.sync.aligned.m16n8k16.row.col.f32.bf16.bf16.f32 "
                 "{%0,%1,%2,%3}, {%4,%5,%6,%7}, {%8,%9}, {%0,%1,%2,%3};\n"
                 : "+f"(c[0]), "+f"(c[1]), "+f"(c[2]), "+f"(c[3])
                 : "r"(a[0]), "r"(a[1]), "r"(a[2]), "r"(a[3]), "r"(b[0]), "r"(b[1]));
}
__device__ __forceinline__ void cpasync16(unsigned dst, const void* src)
{
    asm volatile("cp.async.cg.shared.global [%0], [%1], 16;\n" :: "r"(dst), "l"(src));
}
__device__ __forceinline__ void split_store(bf16* hi, bf16* lo, size_t i, float v)
{
    bf16 h = __float2bfloat16_rn(v);
    hi[i] = h;
    lo[i] = __float2bfloat16_rn(v - __bfloat162float(h));
}

// ------------------------------ GEMM tile ----------------------------------
struct Epi {
    const float *bias, *X;
    float *Cf;
    bf16 *Chi, *Clo;
    int epi, transOut, ldh, ldc, mrow0;
};

// C(128x64 tile at m0,n0) = epi( A1@B1^T [+ A2@B2^T] + bias ), 3-way bf16 split.
// BK=64, 2-buffer cp.async pipeline, ONE __syncthreads per K-iteration.
__device__ void gemm_tile(char* smem, int m0, int n0,
    const bf16* A1h, const bf16* A1l, int lda1,
    const bf16* B1h, const bf16* B1l, int ldb1, int K1,
    const bf16* A2h, const bf16* A2l, int lda2,
    const bf16* B2h, const bf16* B2l, int ldb2, int K2,
    Epi e)
{
    constexpr int BM = 128, BN = 64;
    constexpr int BK = 64, PK = 72;
    constexpr int ASZ = 2 * BM * PK, BSZ = 2 * BN * PK, BUF = ASZ + BSZ;
    bf16* sb = (bf16*)smem;
    const unsigned s0 = (unsigned)__cvta_generic_to_shared(sb);
    const int tid = threadIdx.x, lane = tid & 31, warp = tid >> 5;
    const int wm = (warp & 3) * (BM / 4), wn = (warp >> 2) * (BN / 2);
    constexpr int MT = 2, NT8 = 4;

    float c[MT][NT8][4];
#pragma unroll
    for (int i = 0; i < MT; i++)
#pragma unroll
        for (int j = 0; j < NT8; j++)
#pragma unroll
            for (int el = 0; el < 4; el++) c[i][j][el] = 0.f;

    auto issue = [&](int buf, int k0, const bf16* Ah, const bf16* Al, int lda,
                     const bf16* Bh, const bf16* Bl, int ldb) {
        const unsigned base = s0 + (unsigned)(buf * BUF * 2);
#pragma unroll
        for (int q = 0; q < (BM * 16) / NTHR; q++) {     // 8
            int idx = q * NTHR + tid, row = idx >> 4, sub = idx & 15;
            int s = sub >> 3, kc = sub & 7;
            const bf16* src = (s ? Al : Ah) + (size_t)(m0 + row) * lda + k0 + kc * 8;
            cpasync16(base + (unsigned)(((s * BM + row) * PK + kc * 8) * 2), src);
        }
#pragma unroll
        for (int q = 0; q < (BN * 16) / NTHR; q++) {     // 4
            int idx = q * NTHR + tid, row = idx >> 4, sub = idx & 15;
            int s = sub >> 3, kc = sub & 7;
            const bf16* src = (s ? Bl : Bh) + (size_t)(n0 + row) * ldb + k0 + kc * 8;
            cpasync16(base + (unsigned)((ASZ + (s * BN + row) * PK + kc * 8) * 2), src);
        }
        asm volatile("cp.async.commit_group;\n");
    };

    const int a_row = lane & 15, a_col = (lane >> 4) * 8;
    const int gq = lane >> 3, rr = lane & 7;
    const int b_row = ((gq >> 1) << 3) + rr, b_col = (gq & 1) * 8;

    auto compute = [&](int buf) {
        const unsigned aB = s0 + (unsigned)(buf * BUF * 2);
        const unsigned bB = aB + (unsigned)(ASZ * 2);
#pragma unroll
        for (int kk = 0; kk < 4; ++kk) {
            const int ks = kk * 16;
            unsigned af[2][MT][4];
#pragma unroll
            for (int s = 0; s < 2; s++)
#pragma unroll
                for (int mt = 0; mt < MT; mt++)
                    ldmat4(af[s][mt][0], af[s][mt][1], af[s][mt][2], af[s][mt][3],
                           aB + (unsigned)(((s * BM + wm + mt * 16 + a_row) * PK + ks + a_col) * 2));
            unsigned bfr[2][NT8][2];
#pragma unroll
            for (int s = 0; s < 2; s++)
#pragma unroll
                for (int p = 0; p < NT8 / 2; p++) {
                    unsigned r0, r1, r2, r3;
                    ldmat4(r0, r1, r2, r3,
                           bB + (unsigned)(((s * BN + wn + p * 16 + b_row) * PK + ks + b_col) * 2));
                    bfr[s][2 * p][0] = r0;  bfr[s][2 * p][1] = r1;
                    bfr[s][2 * p + 1][0] = r2;  bfr[s][2 * p + 1][1] = r3;
                }
#pragma unroll
            for (int mt = 0; mt < MT; mt++)
#pragma unroll
                for (int nt = 0; nt < NT8; nt++) {
                    mma16816(c[mt][nt], af[0][mt], bfr[0][nt]);
                    mma16816(c[mt][nt], af[0][mt], bfr[1][nt]);
                    mma16816(c[mt][nt], af[1][mt], bfr[0][nt]);
                }
        }
    };

    const int nk1 = K1 / BK, nk2 = K2 / BK, nk = nk1 + nk2;
    auto issue_t = [&](int t) {
        if (t < nk1) issue(t & 1, t * BK, A1h, A1l, lda1, B1h, B1l, ldb1);
        else         issue(t & 1, (t - nk1) * BK, A2h, A2l, lda2, B2h, B2l, ldb2);
    };

    issue_t(0);
    for (int i = 0; i < nk; i++) {
        asm volatile("cp.async.wait_group 0;\n");   // buf i ready
        __syncthreads();                            // + compute(i-1) done by all
        if (i + 1 < nk) issue_t(i + 1);
        compute(i & 1);
    }
    __syncthreads();

    // epilogue
#pragma unroll
    for (int mt = 0; mt < MT; mt++)
#pragma unroll
        for (int nt = 0; nt < NT8; nt++)
#pragma unroll
            for (int el = 0; el < 4; el++) {
                int m = m0 + wm + mt * 16 + (lane >> 2) + ((el >> 1) << 3);
                int n = n0 + wn + nt * 8 + ((lane & 3) << 1) + (el & 1);
                float v = c[mt][nt][el];
                if (e.bias) v += e.bias[n];
                switch (e.epi) {
                    case 1: v = 0.5f * v * (1.f + erff(v * 0.70710678118654752f)); break;
                    case 2: v = tanhf(v) * PI_F; break;
                    case 3: v = (v > 20.f ? v : log1pf(expf(v))) + 0.1f; break;
                    case 4: v += e.X[(size_t)m * e.ldc + n]; break;
                    case 5: if (n > m) v = 0.f; break;
                    case 6: v *= rsqrtf((float)(e.mrow0 + m + 1) * (float)KK); break;
                }
                if (e.Cf) e.Cf[(size_t)m * e.ldc + n] = v;
                if (e.Chi) {
                    size_t oi = e.transOut ? ((size_t)n * e.ldh + m)
                                           : ((size_t)m * e.ldh + n);
                    split_store(e.Chi, e.Clo, oi, v);
                }
            }
}

// ------------------------------ megakernel ---------------------------------
struct MParams {
    const float *x, *ke_w1, *ke_b1, *ke_w2, *ke_b2, *qe_w1, *qe_b1, *qe_w2, *qe_b2,
                *amp_w, *amp_b, *v_w, *v_b, *ln_g, *ln_b, *out_w, *out_b;
    float* out;
};

__global__ __launch_bounds__(NTHR, 2) void mega(MParams p)
{
    extern __shared__ char smem[];
    const int bid = blockIdx.x, tid = threadIdx.x;
    const int lane = tid & 31, warp = tid >> 5;
    const int gt = bid * NTHR + tid, GS = NBLK * NTHR;

    // ---- S0: convert x (grid-stride) + smem-tiled weight transposes
    for (int i = gt; i < LL * DD; i += GS) split_store(g_xhi, g_xlo, i, p.x[i]);
    {
        float (*ts)[65] = (float(*)[65])smem;        // 64x65 floats
        const float* s4[4] = { p.ke_w1, p.qe_w1, p.v_w, p.out_w };
        bf16* dh4[4] = { g_w1th, g_w1th + DD*DD, g_w1th + 2*DD*DD, g_owth };
        bf16* dl4[4] = { g_w1tl, g_w1tl + DD*DD, g_w1tl + 2*DD*DD, g_owtl };
        for (int t = bid; t < 280; t += NBLK) {
            const float* src; bf16 *dh, *dl; int Kd, Nd, k0, n0;
            if (t < 256) {
                int w = t >> 6, tile = t & 63;
                src = s4[w]; dh = dh4[w]; dl = dl4[w]; Kd = DD; Nd = DD;
                k0 = (tile >> 3) * 64; n0 = (tile & 7) * 64;
            } else {
                int u = t - 256, w = u / 8;
                src = (w == 0) ? p.ke_w2 : (w == 1) ? p.qe_w2 : p.amp_w;
                dh = g_w2th + (size_t)w*KK*DD; dl = g_w2tl + (size_t)w*KK*DD;
                Kd = DD; Nd = KK; k0 = (u % 8) * 64; n0 = 0;
            }
#pragma unroll
            for (int q = 0; q < 16; q++) {
                int idx = q * NTHR + tid, r = idx >> 6, cc = idx & 63;
                ts[r][cc] = src[(size_t)(k0 + r) * Nd + n0 + cc];
            }
            __syncthreads();
#pragma unroll
            for (int q = 0; q < 16; q++) {
                int idx = q * NTHR + tid, nn = idx >> 6, kk2 = idx & 63;
                split_store(dh, dl, (size_t)(n0 + nn) * Kd + k0 + kk2, ts[kk2][nn]);
            }
            __syncthreads();
        }
    }
    grid_sync();

    // ---- S1: Hke/Hqe/VT (384 tiles) + amp (16 tiles)
    for (int t = bid; t < 400; t += NBLK) {
        if (t < 384) {
            int z = t / 128, r = t % 128, m0 = (r >> 3) * 128, n0 = (r & 7) * 64;
            const bf16* Bh = g_w1th + (size_t)z * DD * DD;
            const bf16* Bl = g_w1tl + (size_t)z * DD * DD;
            Epi e{}; e.ldc = DD; e.ldh = DD;
            if (z == 0)      { e.bias = p.ke_b1; e.epi = 1; e.Chi = g_Hkeh; e.Clo = g_Hkel; }
            else if (z == 1) { e.bias = p.qe_b1; e.epi = 1; e.Chi = g_Hqeh; e.Clo = g_Hqel; }
            else             { e.bias = p.v_b;   e.epi = 0; e.Chi = g_VTh;  e.Clo = g_VTl;
                               e.transOut = 1; e.ldh = LL; }
            gemm_tile(smem, m0, n0, g_xhi, g_xlo, DD, Bh, Bl, DD, DD,
                      nullptr, nullptr, 0, nullptr, nullptr, 0, 0, e);
        } else {
            int m0 = (t - 384) * 128;
            Epi e{}; e.ldc = KK; e.bias = p.amp_b; e.epi = 3; e.Cf = g_amp;
            gemm_tile(smem, m0, 0, g_xhi, g_xlo, DD,
                      g_w2th + (size_t)2*KK*DD, g_w2tl + (size_t)2*KK*DD, DD, DD,
                      nullptr, nullptr, 0, nullptr, nullptr, 0, 0, e);
        }
    }
    grid_sync();

    // ---- S2: pk/pq (32 tiles)
    for (int t = bid; t < 32; t += NBLK) {
        int z = t / 16, m0 = (t % 16) * 128;
        Epi e{}; e.ldc = KK; e.epi = 2;
        const bf16 *Ah, *Al;
        if (z == 0) { Ah = g_Hkeh; Al = g_Hkel; e.bias = p.ke_b2; e.Cf = g_pk; }
        else        { Ah = g_Hqeh; Al = g_Hqel; e.bias = p.qe_b2; e.Cf = g_pq; }
        gemm_tile(smem, m0, 0, Ah, Al, DD,
                  g_w2th + (size_t)z*KK*DD, g_w2tl + (size_t)z*KK*DD, DD, DD,
                  nullptr, nullptr, 0, nullptr, nullptr, 0, 0, e);
    }
    grid_sync();

    // ---- S3: phasors (64 tiles of 32l x 64k; KcT staged through smem)
    {
        float (*skr)[33] = (float(*)[33])smem;                 // [64][33]
        float (*ski)[33] = (float(*)[33])(smem + 64*33*4);
        for (int t = bid; t < 64; t += NBLK) {
            int l0 = t * 32;
#pragma unroll
            for (int q = 0; q < 8; q++) {
                int idx = q * NTHR + tid, l = idx >> 6, k = idx & 63;
                size_t gi = (size_t)(l0 + l) * KK + k;
                float a = g_amp[gi], s, cc;
                sincosf(g_pk[gi], &s, &cc);
                float kr = a * cc, ki = a * s;
                split_store(g_Kch, g_Kcl, (size_t)(l0 + l) * TWOK + k,      kr);
                split_store(g_Kch, g_Kcl, (size_t)(l0 + l) * TWOK + KK + k, ki);
                skr[k][l] = kr; ski[k][l] = ki;
                sincosf(g_pq[gi], &s, &cc);
                split_store(g_Qch, g_Qcl, (size_t)(l0 + l) * TWOK + k,      a * cc);
                split_store(g_Qch, g_Qcl, (size_t)(l0 + l) * TWOK + KK + k, a * s);
            }
            __syncthreads();
#pragma unroll
            for (int q = 0; q < 8; q++) {
                int idx = q * NTHR + tid, k = idx >> 5, l = idx & 31;
                split_store(g_KcTh, g_KcTl, (size_t)k * LL + l0 + l,        skr[k][l]);
                split_store(g_KcTh, g_KcTl, (size_t)(k + KK) * LL + l0 + l, ski[k][l]);
            }
            __syncthreads();
        }
    }
    grid_sync();

    // ---- S4: GT = VT@KcT^T (128 tiles) + P = tril(Q@Kc^T) (32 tiles)
    for (int t = bid; t < 160; t += NBLK) {
        if (t < 128) {
            int z = t >> 3, r = t & 7, m0 = (r >> 1) * 128, n0 = (r & 1) * 64;
            Epi e{}; e.ldc = TWOK; e.epi = 0; e.Cf = g_GT + (size_t)z * DD * TWOK;
            gemm_tile(smem, m0, n0,
                g_VTh + (size_t)z * CH,  g_VTl + (size_t)z * CH,  LL,
                g_KcTh + (size_t)z * CH, g_KcTl + (size_t)z * CH, LL, CH,
                nullptr, nullptr, 0, nullptr, nullptr, 0, 0, e);
        } else {
            int u = t - 128, z = u >> 1, n0 = (u & 1) * 64;
            Epi e{}; e.ldc = CH; e.ldh = CH; e.epi = 5;
            e.Chi = g_Ph + (size_t)z * CH * CH; e.Clo = g_Pl + (size_t)z * CH * CH;
            gemm_tile(smem, 0, n0,
                g_Qch + (size_t)z * CH * TWOK, g_Qcl + (size_t)z * CH * TWOK, TWOK,
                g_Kch + (size_t)z * CH * TWOK, g_Kcl + (size_t)z * CH * TWOK, TWOK, TWOK,
                nullptr, nullptr, 0, nullptr, nullptr, 0, 0, e);
        }
    }
    grid_sync();

    // ---- S5: exclusive chunk scan (coalesced)
    for (int i = gt; i < TWOK * DD; i += GS) {
        float run = 0.f;
#pragma unroll
        for (int cch = 0; cch < NCH; cch++) {
            split_store(g_SxTh, g_SxTl, (size_t)cch * DD * TWOK + i, run);
            run += g_GT[(size_t)cch * DD * TWOK + i];
        }
    }
    grid_sync();

    // ---- S6: ret = (Q@Sx + P@V) * rsqrt((l+1)K)  (128 tiles, fused 2-phase)
    for (int t = bid; t < 128; t += NBLK) {
        int z = t >> 3, n0 = (t & 7) * 64;
        Epi e{}; e.ldc = DD; e.epi = 6; e.mrow0 = z * CH;
        e.Cf = g_ret + (size_t)z * CH * DD;
        gemm_tile(smem, 0, n0,
            g_Qch  + (size_t)z * CH * TWOK, g_Qcl  + (size_t)z * CH * TWOK, TWOK,
            g_SxTh + (size_t)z * DD * TWOK, g_SxTl + (size_t)z * DD * TWOK, TWOK, TWOK,
            g_Ph   + (size_t)z * CH * CH,   g_Pl   + (size_t)z * CH * CH,   CH,
            g_VTh  + (size_t)z * CH,        g_VTl  + (size_t)z * CH,        LL, CH,
            e);
    }
    grid_sync();

    // ---- S7: LayerNorm (one warp per row, shuffle reductions)
    for (int row = bid * 8 + warp; row < LL; row += NBLK * 8) {
        const float4* r4 = (const float4*)(g_ret + (size_t)row * DD);
        float4 v[4];
        float sum = 0.f;
#pragma unroll
        for (int w = 0; w < 4; w++) {
            v[w] = r4[lane + w * 32];
            sum += v[w].x + v[w].y + v[w].z + v[w].w;
        }
#pragma unroll
        for (int o = 16; o > 0; o >>= 1) sum += __shfl_xor_sync(0xffffffffu, sum, o);
        float mu = sum * (1.f / DD);
        float var = 0.f;
#pragma unroll
        for (int w = 0; w < 4; w++) {
            float a0 = v[w].x - mu, a1 = v[w].y - mu, a2 = v[w].z - mu, a3 = v[w].w - mu;
            var += a0*a0 + a1*a1 + a2*a2 + a3*a3;
        }
#pragma unroll
        for (int o = 16; o > 0; o >>= 1) var += __shfl_xor_sync(0xffffffffu, var, o);
        float inv = rsqrtf(var * (1.f / DD) + 1e-5f);
#pragma unroll
        for (int w = 0; w < 4; w++) {
            int n = (lane + w * 32) * 4;
            float o0 = (v[w].x - mu) * inv * p.ln_g[n]     + p.ln_b[n];
            float o1 = (v[w].y - mu) * inv * p.ln_g[n + 1] + p.ln_b[n + 1];
            float o2 = (v[w].z - mu) * inv * p.ln_g[n + 2] + p.ln_b[n + 2];
            float o3 = (v[w].w - mu) * inv * p.ln_g[n + 3] + p.ln_b[n + 3];
            split_store(g_rnh, g_rnl, (size_t)row * DD + n,     o0);
            split_store(g_rnh, g_rnl, (size_t)row * DD + n + 1, o1);
            split_store(g_rnh, g_rnl, (size_t)row * DD + n + 2, o2);
            split_store(g_rnh, g_rnl, (size_t)row * DD + n + 3, o3);
        }
    }
    grid_sync();

    // ---- S8: out = x + rn @ out_w + out_b  (128 tiles)
    for (int t = bid; t < 128; t += NBLK) {
        int m0 = (t >> 3) * 128, n0 = (t & 7) * 64;
        Epi e{}; e.ldc = DD; e.epi = 4; e.X = p.x; e.bias = p.out_b; e.Cf = p.out;
        gemm_tile(smem, m0, n0, g_rnh, g_rnl, DD, g_owth, g_owtl, DD, DD,
                  nullptr, nullptr, 0, nullptr, nullptr, 0, 0, e);
    }
}

// ------------------------------ host ---------------------------------------
extern "C" void kernel_launch(void* const* d_in, const int* in_sizes, int n_in,
                              void* d_out, int out_size)
{
    MParams p;
    p.x     = (const float*)d_in[0];
    p.ke_w1 = (const float*)d_in[1];   p.ke_b1 = (const float*)d_in[2];
    p.ke_w2 = (const float*)d_in[3];   p.ke_b2 = (const float*)d_in[4];
    p.qe_w1 = (const float*)d_in[5];   p.qe_b1 = (const float*)d_in[6];
    p.qe_w2 = (const float*)d_in[7];   p.qe_b2 = (const float*)d_in[8];
    p.amp_w = (const float*)d_in[9];   p.amp_b = (const float*)d_in[10];
    p.v_w   = (const float*)d_in[11];  p.v_b   = (const float*)d_in[12];
    p.ln_g  = (const float*)d_in[13];  p.ln_b  = (const float*)d_in[14];
    p.out_w = (const float*)d_in[15];  p.out_b = (const float*)d_in[16];
    p.out   = (float*)d_out;

    // 2 buffers x (A: 2*128*72 + B: 2*64*72) bf16 x 2B = 110592 bytes
    const int SMEM = 2 * (2 * 128 * 72 + 2 * 64 * 72) * 2;
    cudaFuncSetAttribute(mega, cudaFuncAttributeMaxDynamicSharedMemorySize, SMEM);
    mega<<<NBLK, NTHR, SMEM>>>(p);

    (void)in_sizes; (void)n_in; (void)out_size;
}

// round 7
// speedup vs baseline: 2.3255x; 1.0843x over previous
#include <cuda_runtime.h>
#include <cuda_bf16.h>
#include <math.h>

#define LL   2048
#define DD   512
#define KK   64
#define TWOK 128
#define CH   128
#define NCH  16
#define PI_F 3.14159265358979323846f
#define NBLK 444
#define NTHR 256

typedef __nv_bfloat16 bf16;

// ------------------------------ buffers -----------------------------------
static __device__ bf16  g_xhi [LL*DD],      g_xlo [LL*DD];
static __device__ bf16  g_w1th[3*DD*DD],    g_w1tl[3*DD*DD];
static __device__ bf16  g_owth[DD*DD],      g_owtl[DD*DD];
static __device__ bf16  g_w2th[3*KK*DD],    g_w2tl[3*KK*DD];
static __device__ bf16  g_Hkeh[LL*DD],      g_Hkel[LL*DD];
static __device__ bf16  g_Hqeh[LL*DD],      g_Hqel[LL*DD];
static __device__ bf16  g_VTh [DD*LL],      g_VTl [DD*LL];
static __device__ float g_pk  [LL*KK], g_pq[LL*KK], g_amp[LL*KK];
static __device__ bf16  g_Qch [LL*TWOK],    g_Qcl [LL*TWOK];
static __device__ bf16  g_Kch [LL*TWOK],    g_Kcl [LL*TWOK];
static __device__ bf16  g_KcTh[TWOK*LL],    g_KcTl[TWOK*LL];
static __device__ float g_GT  [NCH*DD*TWOK];                 // [c][d][kk]
static __device__ bf16  g_SxTh[NCH*DD*TWOK],g_SxTl[NCH*DD*TWOK];
static __device__ bf16  g_Ph  [NCH*CH*CH],  g_Pl  [NCH*CH*CH];
static __device__ float g_ret [LL*DD];
static __device__ bf16  g_rnh [LL*DD],      g_rnl [LL*DD];

__device__ unsigned g_bar, g_gen;

// ------------------------------ grid barrier -------------------------------
__device__ __forceinline__ void grid_sync()
{
    __syncthreads();
    if (threadIdx.x == 0) {
        unsigned g = *(volatile unsigned*)&g_gen;
        __threadfence();
        unsigned t = atomicAdd(&g_bar, 1u);
        if (t == NBLK - 1) {
            atomicExch(&g_bar, 0u);
            __threadfence();
            atomicAdd(&g_gen, 1u);
        } else {
            while (*(volatile unsigned*)&g_gen == g) { __nanosleep(32); }
        }
        __threadfence();
    }
    __syncthreads();
}

// ------------------------------ PTX helpers --------------------------------
__device__ __forceinline__ void ldmat4(unsigned& r0, unsigned& r1,
                                       unsigned& r2, unsigned& r3, unsigned addr)
{
    asm volatile("ldmatrix.sync.aligned.m8n8.x4.shared.b16 {%0,%1,%2,%3}, [%4];\n"
                 : "=r"(r0), "=r"(r1), "=r"(r2), "=r"(r3) : "r"(addr));
}
__device__ __forceinline__ void mma16816(float* c, const unsigned* a, const unsigned* b)
{
    asm volatile("mma.sync.aligned.m16n8k16.row.col.f32.bf16.bf16.f32 "
                 "{%0,%1,%2,%3}, {%4,%5,%6,%7}, {%8,%9}, {%0,%1,%2,%3};\n"
                 : "+f"(c[0]), "+f"(c[1]), "+f"(c[2]), "+f"(c[3])
                 : "r"(a[0]), "r"(a[1]), "r"(a[2]), "r"(a[3]), "r"(b[0]), "r"(b[1]));
}
__device__ __forceinline__ void cpasync16(unsigned dst, const void* src)
{
    asm volatile("cp.async.cg.shared.global [%0], [%1], 16;\n" :: "r"(dst), "l"(src));
}
__device__ __forceinline__ void split_store(bf16* hi, bf16* lo, size_t i, float v)
{
    bf16 h = __float2bfloat16_rn(v);
    hi[i] = h;
    lo[i] = __float2bfloat16_rn(v - __bfloat162float(h));
}

// ------------------------------ GEMM tile ----------------------------------
struct Epi {
    const float *bias, *X;
    float *Cf;
    bf16 *Chi, *Clo;
    int epi, transOut, ldh, ldc, mrow0;
};

// C(64x64 tile at m0,n0) = epi( A1@B1^T [+ A2@B2^T] + bias ), 3-way bf16 split.
// BK=64, 2-buffer cp.async pipeline, ONE __syncthreads per K-iteration.
__device__ void gemm_tile(char* smem, int m0, int n0,
    const bf16* A1h, const bf16* A1l, int lda1,
    const bf16* B1h, const bf16* B1l, int ldb1, int K1,
    const bf16* A2h, const bf16* A2l, int lda2,
    const bf16* B2h, const bf16* B2l, int ldb2, int K2,
    Epi e)
{
    constexpr int BM = 64, BN = 64;
    constexpr int BK = 64, PK = 72;
    constexpr int ASZ = 2 * BM * PK, BSZ = 2 * BN * PK, BUF = ASZ + BSZ;
    bf16* sb = (bf16*)smem;
    const unsigned s0 = (unsigned)__cvta_generic_to_shared(sb);
    const int tid = threadIdx.x, lane = tid & 31, warp = tid >> 5;
    // 8 warps: 2 (m) x 4 (n); each warp 32 rows x 16 cols
    const int wm = (warp & 1) * 32, wn = (warp >> 1) * 16;
    constexpr int MT = 2, NT8 = 2;

    float c[MT][NT8][4];
#pragma unroll
    for (int i = 0; i < MT; i++)
#pragma unroll
        for (int j = 0; j < NT8; j++)
#pragma unroll
            for (int el = 0; el < 4; el++) c[i][j][el] = 0.f;

    auto issue = [&](int buf, int k0, const bf16* Ah, const bf16* Al, int lda,
                     const bf16* Bh, const bf16* Bl, int ldb) {
        const unsigned base = s0 + (unsigned)(buf * BUF * 2);
#pragma unroll
        for (int q = 0; q < (BM * 16) / NTHR; q++) {     // 4
            int idx = q * NTHR + tid, row = idx >> 4, sub = idx & 15;
            int s = sub >> 3, kc = sub & 7;
            const bf16* src = (s ? Al : Ah) + (size_t)(m0 + row) * lda + k0 + kc * 8;
            cpasync16(base + (unsigned)(((s * BM + row) * PK + kc * 8) * 2), src);
        }
#pragma unroll
        for (int q = 0; q < (BN * 16) / NTHR; q++) {     // 4
            int idx = q * NTHR + tid, row = idx >> 4, sub = idx & 15;
            int s = sub >> 3, kc = sub & 7;
            const bf16* src = (s ? Bl : Bh) + (size_t)(n0 + row) * ldb + k0 + kc * 8;
            cpasync16(base + (unsigned)((ASZ + (s * BN + row) * PK + kc * 8) * 2), src);
        }
        asm volatile("cp.async.commit_group;\n");
    };

    const int a_row = lane & 15, a_col = (lane >> 4) * 8;
    const int gq = lane >> 3, rr = lane & 7;
    const int b_row = ((gq >> 1) << 3) + rr, b_col = (gq & 1) * 8;

    auto compute = [&](int buf) {
        const unsigned aB = s0 + (unsigned)(buf * BUF * 2);
        const unsigned bB = aB + (unsigned)(ASZ * 2);
#pragma unroll
        for (int kk = 0; kk < 4; ++kk) {
            const int ks = kk * 16;
            unsigned af[2][MT][4];
#pragma unroll
            for (int s = 0; s < 2; s++)
#pragma unroll
                for (int mt = 0; mt < MT; mt++)
                    ldmat4(af[s][mt][0], af[s][mt][1], af[s][mt][2], af[s][mt][3],
                           aB + (unsigned)(((s * BM + wm + mt * 16 + a_row) * PK + ks + a_col) * 2));
            unsigned bfr[2][NT8][2];
#pragma unroll
            for (int s = 0; s < 2; s++) {
                unsigned r0, r1, r2, r3;
                ldmat4(r0, r1, r2, r3,
                       bB + (unsigned)(((s * BN + wn + b_row) * PK + ks + b_col) * 2));
                bfr[s][0][0] = r0;  bfr[s][0][1] = r1;
                bfr[s][1][0] = r2;  bfr[s][1][1] = r3;
            }
#pragma unroll
            for (int mt = 0; mt < MT; mt++)
#pragma unroll
                for (int nt = 0; nt < NT8; nt++) {
                    mma16816(c[mt][nt], af[0][mt], bfr[0][nt]);
                    mma16816(c[mt][nt], af[0][mt], bfr[1][nt]);
                    mma16816(c[mt][nt], af[1][mt], bfr[0][nt]);
                }
        }
    };

    const int nk1 = K1 / BK, nk2 = K2 / BK, nk = nk1 + nk2;
    auto issue_t = [&](int t) {
        if (t < nk1) issue(t & 1, t * BK, A1h, A1l, lda1, B1h, B1l, ldb1);
        else         issue(t & 1, (t - nk1) * BK, A2h, A2l, lda2, B2h, B2l, ldb2);
    };

    issue_t(0);
    for (int i = 0; i < nk; i++) {
        asm volatile("cp.async.wait_group 0;\n");
        __syncthreads();
        if (i + 1 < nk) issue_t(i + 1);
        compute(i & 1);
    }
    __syncthreads();

    // epilogue
#pragma unroll
    for (int mt = 0; mt < MT; mt++)
#pragma unroll
        for (int nt = 0; nt < NT8; nt++)
#pragma unroll
            for (int el = 0; el < 4; el++) {
                int m = m0 + wm + mt * 16 + (lane >> 2) + ((el >> 1) << 3);
                int n = n0 + wn + nt * 8 + ((lane & 3) << 1) + (el & 1);
                float v = c[mt][nt][el];
                if (e.bias) v += e.bias[n];
                switch (e.epi) {
                    case 1: v = 0.5f * v * (1.f + erff(v * 0.70710678118654752f)); break;
                    case 2: v = tanhf(v) * PI_F; break;
                    case 3: v = (v > 20.f ? v : log1pf(expf(v))) + 0.1f; break;
                    case 4: v += e.X[(size_t)m * e.ldc + n]; break;
                    case 5: if (n > m) v = 0.f; break;
                    case 6: v *= rsqrtf((float)(e.mrow0 + m + 1) * (float)KK); break;
                }
                if (e.Cf) e.Cf[(size_t)m * e.ldc + n] = v;
                if (e.Chi) {
                    size_t oi = e.transOut ? ((size_t)n * e.ldh + m)
                                           : ((size_t)m * e.ldh + n);
                    split_store(e.Chi, e.Clo, oi, v);
                }
            }
}

// ------------------------------ megakernel ---------------------------------
struct MParams {
    const float *x, *ke_w1, *ke_b1, *ke_w2, *ke_b2, *qe_w1, *qe_b1, *qe_w2, *qe_b2,
                *amp_w, *amp_b, *v_w, *v_b, *ln_g, *ln_b, *out_w, *out_b;
    float* out;
};

__global__ __launch_bounds__(NTHR, 3) void mega(MParams p)
{
    extern __shared__ char smem[];
    const int bid = blockIdx.x, tid = threadIdx.x;
    const int lane = tid & 31, warp = tid >> 5;
    const int gt = bid * NTHR + tid, GS = NBLK * NTHR;

    // ---- S0: convert x (grid-stride) + smem-tiled weight transposes
    for (int i = gt; i < LL * DD; i += GS) split_store(g_xhi, g_xlo, i, p.x[i]);
    {
        float (*ts)[65] = (float(*)[65])smem;        // 64x65 floats
        const float* s4[4] = { p.ke_w1, p.qe_w1, p.v_w, p.out_w };
        bf16* dh4[4] = { g_w1th, g_w1th + DD*DD, g_w1th + 2*DD*DD, g_owth };
        bf16* dl4[4] = { g_w1tl, g_w1tl + DD*DD, g_w1tl + 2*DD*DD, g_owtl };
        for (int t = bid; t < 280; t += NBLK) {
            const float* src; bf16 *dh, *dl; int Kd, Nd, k0, n0;
            if (t < 256) {
                int w = t >> 6, tile = t & 63;
                src = s4[w]; dh = dh4[w]; dl = dl4[w]; Kd = DD; Nd = DD;
                k0 = (tile >> 3) * 64; n0 = (tile & 7) * 64;
            } else {
                int u = t - 256, w = u / 8;
                src = (w == 0) ? p.ke_w2 : (w == 1) ? p.qe_w2 : p.amp_w;
                dh = g_w2th + (size_t)w*KK*DD; dl = g_w2tl + (size_t)w*KK*DD;
                Kd = DD; Nd = KK; k0 = (u % 8) * 64; n0 = 0;
            }
#pragma unroll
            for (int q = 0; q < 16; q++) {
                int idx = q * NTHR + tid, r = idx >> 6, cc = idx & 63;
                ts[r][cc] = src[(size_t)(k0 + r) * Nd + n0 + cc];
            }
            __syncthreads();
#pragma unroll
            for (int q = 0; q < 16; q++) {
                int idx = q * NTHR + tid, nn = idx >> 6, kk2 = idx & 63;
                split_store(dh, dl, (size_t)(n0 + nn) * Kd + k0 + kk2, ts[kk2][nn]);
            }
            __syncthreads();
        }
    }
    grid_sync();

    // ---- S1: Hke/Hqe/VT (768 tiles) + amp (32 tiles)
    for (int t = bid; t < 800; t += NBLK) {
        if (t < 768) {
            int z = t / 256, r = t % 256, m0 = (r >> 3) * 64, n0 = (r & 7) * 64;
            const bf16* Bh = g_w1th + (size_t)z * DD * DD;
            const bf16* Bl = g_w1tl + (size_t)z * DD * DD;
            Epi e{}; e.ldc = DD; e.ldh = DD;
            if (z == 0)      { e.bias = p.ke_b1; e.epi = 1; e.Chi = g_Hkeh; e.Clo = g_Hkel; }
            else if (z == 1) { e.bias = p.qe_b1; e.epi = 1; e.Chi = g_Hqeh; e.Clo = g_Hqel; }
            else             { e.bias = p.v_b;   e.epi = 0; e.Chi = g_VTh;  e.Clo = g_VTl;
                               e.transOut = 1; e.ldh = LL; }
            gemm_tile(smem, m0, n0, g_xhi, g_xlo, DD, Bh, Bl, DD, DD,
                      nullptr, nullptr, 0, nullptr, nullptr, 0, 0, e);
        } else {
            int m0 = (t - 768) * 64;
            Epi e{}; e.ldc = KK; e.bias = p.amp_b; e.epi = 3; e.Cf = g_amp;
            gemm_tile(smem, m0, 0, g_xhi, g_xlo, DD,
                      g_w2th + (size_t)2*KK*DD, g_w2tl + (size_t)2*KK*DD, DD, DD,
                      nullptr, nullptr, 0, nullptr, nullptr, 0, 0, e);
        }
    }
    grid_sync();

    // ---- S2: pk/pq (64 tiles)
    for (int t = bid; t < 64; t += NBLK) {
        int z = t / 32, m0 = (t % 32) * 64;
        Epi e{}; e.ldc = KK; e.epi = 2;
        const bf16 *Ah, *Al;
        if (z == 0) { Ah = g_Hkeh; Al = g_Hkel; e.bias = p.ke_b2; e.Cf = g_pk; }
        else        { Ah = g_Hqeh; Al = g_Hqel; e.bias = p.qe_b2; e.Cf = g_pq; }
        gemm_tile(smem, m0, 0, Ah, Al, DD,
                  g_w2th + (size_t)z*KK*DD, g_w2tl + (size_t)z*KK*DD, DD, DD,
                  nullptr, nullptr, 0, nullptr, nullptr, 0, 0, e);
    }
    grid_sync();

    // ---- S3: phasors (64 tiles of 32l x 64k; KcT staged through smem)
    {
        float (*skr)[33] = (float(*)[33])smem;                 // [64][33]
        float (*ski)[33] = (float(*)[33])(smem + 64*33*4);
        for (int t = bid; t < 64; t += NBLK) {
            int l0 = t * 32;
#pragma unroll
            for (int q = 0; q < 8; q++) {
                int idx = q * NTHR + tid, l = idx >> 6, k = idx & 63;
                size_t gi = (size_t)(l0 + l) * KK + k;
                float a = g_amp[gi], s, cc;
                sincosf(g_pk[gi], &s, &cc);
                float kr = a * cc, ki = a * s;
                split_store(g_Kch, g_Kcl, (size_t)(l0 + l) * TWOK + k,      kr);
                split_store(g_Kch, g_Kcl, (size_t)(l0 + l) * TWOK + KK + k, ki);
                skr[k][l] = kr; ski[k][l] = ki;
                sincosf(g_pq[gi], &s, &cc);
                split_store(g_Qch, g_Qcl, (size_t)(l0 + l) * TWOK + k,      a * cc);
                split_store(g_Qch, g_Qcl, (size_t)(l0 + l) * TWOK + KK + k, a * s);
            }
            __syncthreads();
#pragma unroll
            for (int q = 0; q < 8; q++) {
                int idx = q * NTHR + tid, k = idx >> 5, l = idx & 31;
                split_store(g_KcTh, g_KcTl, (size_t)k * LL + l0 + l,        skr[k][l]);
                split_store(g_KcTh, g_KcTl, (size_t)(k + KK) * LL + l0 + l, ski[k][l]);
            }
            __syncthreads();
        }
    }
    grid_sync();

    // ---- S4: GT = VT@KcT^T (256 tiles) + P = tril(Q@Kc^T) (64 tiles)
    for (int t = bid; t < 320; t += NBLK) {
        if (t < 256) {
            int z = t >> 4, r = t & 15, m0 = (r >> 1) * 64, n0 = (r & 1) * 64;
            Epi e{}; e.ldc = TWOK; e.epi = 0; e.Cf = g_GT + (size_t)z * DD * TWOK;
            gemm_tile(smem, m0, n0,
                g_VTh + (size_t)z * CH,  g_VTl + (size_t)z * CH,  LL,
                g_KcTh + (size_t)z * CH, g_KcTl + (size_t)z * CH, LL, CH,
                nullptr, nullptr, 0, nullptr, nullptr, 0, 0, e);
        } else {
            int u = t - 256, z = u >> 2, r = u & 3, m0 = (r >> 1) * 64, n0 = (r & 1) * 64;
            Epi e{}; e.ldc = CH; e.ldh = CH; e.epi = 5;
            e.Chi = g_Ph + (size_t)z * CH * CH; e.Clo = g_Pl + (size_t)z * CH * CH;
            gemm_tile(smem, m0, n0,
                g_Qch + (size_t)z * CH * TWOK, g_Qcl + (size_t)z * CH * TWOK, TWOK,
                g_Kch + (size_t)z * CH * TWOK, g_Kcl + (size_t)z * CH * TWOK, TWOK, TWOK,
                nullptr, nullptr, 0, nullptr, nullptr, 0, 0, e);
        }
    }
    grid_sync();

    // ---- S5: exclusive chunk scan (coalesced)
    for (int i = gt; i < TWOK * DD; i += GS) {
        float run = 0.f;
#pragma unroll
        for (int cch = 0; cch < NCH; cch++) {
            split_store(g_SxTh, g_SxTl, (size_t)cch * DD * TWOK + i, run);
            run += g_GT[(size_t)cch * DD * TWOK + i];
        }
    }
    grid_sync();

    // ---- S6: ret = (Q@Sx + P@V) * rsqrt((l+1)K)  (256 tiles, fused 2-phase)
    for (int t = bid; t < 256; t += NBLK) {
        int z = t >> 4, r = t & 15, m0 = (r >> 3) * 64, n0 = (r & 7) * 64;
        Epi e{}; e.ldc = DD; e.epi = 6; e.mrow0 = z * CH;
        e.Cf = g_ret + (size_t)z * CH * DD;
        gemm_tile(smem, m0, n0,
            g_Qch  + (size_t)z * CH * TWOK, g_Qcl  + (size_t)z * CH * TWOK, TWOK,
            g_SxTh + (size_t)z * DD * TWOK, g_SxTl + (size_t)z * DD * TWOK, TWOK, TWOK,
            g_Ph   + (size_t)z * CH * CH,   g_Pl   + (size_t)z * CH * CH,   CH,
            g_VTh  + (size_t)z * CH,        g_VTl  + (size_t)z * CH,        LL, CH,
            e);
    }
    grid_sync();

    // ---- S7: LayerNorm (one warp per row, shuffle reductions)
    for (int row = bid * 8 + warp; row < LL; row += NBLK * 8) {
        const float4* r4 = (const float4*)(g_ret + (size_t)row * DD);
        float4 v[4];
        float sum = 0.f;
#pragma unroll
        for (int w = 0; w < 4; w++) {
            v[w] = r4[lane + w * 32];
            sum += v[w].x + v[w].y + v[w].z + v[w].w;
        }
#pragma unroll
        for (int o = 16; o > 0; o >>= 1) sum += __shfl_xor_sync(0xffffffffu, sum, o);
        float mu = sum * (1.f / DD);
        float var = 0.f;
#pragma unroll
        for (int w = 0; w < 4; w++) {
            float a0 = v[w].x - mu, a1 = v[w].y - mu, a2 = v[w].z - mu, a3 = v[w].w - mu;
            var += a0*a0 + a1*a1 + a2*a2 + a3*a3;
        }
#pragma unroll
        for (int o = 16; o > 0; o >>= 1) var += __shfl_xor_sync(0xffffffffu, var, o);
        float inv = rsqrtf(var * (1.f / DD) + 1e-5f);
#pragma unroll
        for (int w = 0; w < 4; w++) {
            int n = (lane + w * 32) * 4;
            float o0 = (v[w].x - mu) * inv * p.ln_g[n]     + p.ln_b[n];
            float o1 = (v[w].y - mu) * inv * p.ln_g[n + 1] + p.ln_b[n + 1];
            float o2 = (v[w].z - mu) * inv * p.ln_g[n + 2] + p.ln_b[n + 2];
            float o3 = (v[w].w - mu) * inv * p.ln_g[n + 3] + p.ln_b[n + 3];
            split_store(g_rnh, g_rnl, (size_t)row * DD + n,     o0);
            split_store(g_rnh, g_rnl, (size_t)row * DD + n + 1, o1);
            split_store(g_rnh, g_rnl, (size_t)row * DD + n + 2, o2);
            split_store(g_rnh, g_rnl, (size_t)row * DD + n + 3, o3);
        }
    }
    grid_sync();

    // ---- S8: out = x + rn @ out_w + out_b  (256 tiles)
    for (int t = bid; t < 256; t += NBLK) {
        int m0 = (t >> 3) * 64, n0 = (t & 7) * 64;
        Epi e{}; e.ldc = DD; e.epi = 4; e.X = p.x; e.bias = p.out_b; e.Cf = p.out;
        gemm_tile(smem, m0, n0, g_rnh, g_rnl, DD, g_owth, g_owtl, DD, DD,
                  nullptr, nullptr, 0, nullptr, nullptr, 0, 0, e);
    }
}

// ------------------------------ host ---------------------------------------
extern "C" void kernel_launch(void* const* d_in, const int* in_sizes, int n_in,
                              void* d_out, int out_size)
{
    MParams p;
    p.x     = (const float*)d_in[0];
    p.ke_w1 = (const float*)d_in[1];   p.ke_b1 = (const float*)d_in[2];
    p.ke_w2 = (const float*)d_in[3];   p.ke_b2 = (const float*)d_in[4];
    p.qe_w1 = (const float*)d_in[5];   p.qe_b1 = (const float*)d_in[6];
    p.qe_w2 = (const float*)d_in[7];   p.qe_b2 = (const float*)d_in[8];
    p.amp_w = (const float*)d_in[9];   p.amp_b = (const float*)d_in[10];
    p.v_w   = (const float*)d_in[11];  p.v_b   = (const float*)d_in[12];
    p.ln_g  = (const float*)d_in[13];  p.ln_b  = (const float*)d_in[14];
    p.out_w = (const float*)d_in[15];  p.out_b = (const float*)d_in[16];
    p.out   = (float*)d_out;

    // 2 buffers x (A: 2*64*72 + B: 2*64*72) bf16 x 2B = 73728 bytes
    const int SMEM = 2 * (2 * 64 * 72 + 2 * 64 * 72) * 2;
    cudaFuncSetAttribute(mega, cudaFuncAttributeMaxDynamicSharedMemorySize, SMEM);
    mega<<<NBLK, NTHR, SMEM>>>(p);

    (void)in_sizes; (void)n_in; (void)out_size;
}